// round 7
// baseline (speedup 1.0000x reference)
#include <cuda_runtime.h>
#include <cuda_bf16.h>
#include <cstdint>
#include <math.h>

#define BATCH 4
#define HEADS 16
#define SEQ   2048
#define DKDIM 64
#define BH    (BATCH*HEADS)
#define NELEM (BH*SEQ*DKDIM)   // 8,388,608

// Scratch (allowed: __device__ global arrays)
__device__ float g_M[BH * SEQ];
__device__ float g_L[BH * SEQ];
__device__ __nv_bfloat16 g_Qhi[NELEM], g_Qlo[NELEM];
__device__ __nv_bfloat16 g_Khi[NELEM], g_Klo[NELEM];
__device__ __nv_bfloat16 g_Vhi[NELEM], g_Vlo[NELEM];

// ---------------------------------------------------------------------------
// PTX helpers
// ---------------------------------------------------------------------------
__device__ __forceinline__ uint32_t smem_u32(const void* p) {
    uint32_t a;
    asm("{ .reg .u64 t; cvta.to.shared.u64 t, %1; cvt.u32.u64 %0, t; }"
        : "=r"(a) : "l"(p));
    return a;
}
__device__ __forceinline__ void ldsm_x4(uint32_t (&r)[4], uint32_t addr) {
    asm volatile("ldmatrix.sync.aligned.m8n8.x4.shared.b16 {%0,%1,%2,%3}, [%4];"
        : "=r"(r[0]), "=r"(r[1]), "=r"(r[2]), "=r"(r[3]) : "r"(addr));
}
__device__ __forceinline__ void ldsm_x4_t(uint32_t (&r)[4], uint32_t addr) {
    asm volatile("ldmatrix.sync.aligned.m8n8.x4.trans.shared.b16 {%0,%1,%2,%3}, [%4];"
        : "=r"(r[0]), "=r"(r[1]), "=r"(r[2]), "=r"(r[3]) : "r"(addr));
}
__device__ __forceinline__ void mma_bf16(float (&c)[4], const uint32_t (&a)[4],
                                         uint32_t b0, uint32_t b1) {
    asm volatile("mma.sync.aligned.m16n8k16.row.col.f32.bf16.bf16.f32 "
        "{%0,%1,%2,%3}, {%4,%5,%6,%7}, {%8,%9}, {%0,%1,%2,%3};"
        : "+f"(c[0]), "+f"(c[1]), "+f"(c[2]), "+f"(c[3])
        : "r"(a[0]), "r"(a[1]), "r"(a[2]), "r"(a[3]), "r"(b0), "r"(b1));
}
#define CP16(dst, src) \
    asm volatile("cp.async.cg.shared.global [%0], [%1], 16;" \
                 :: "r"(dst), "l"(src) : "memory")
#define CP_COMMIT  asm volatile("cp.async.commit_group;" ::: "memory")
#define CP_WAIT0   asm volatile("cp.async.wait_group 0;" ::: "memory")
#define CP_WAIT1   asm volatile("cp.async.wait_group 1;" ::: "memory")

#define SW128(b) ((b) ^ (((b) >> 3) & 0x70))

__device__ __forceinline__ void split_bf16(float x, uint16_t& hi, uint16_t& lo) {
    __nv_bfloat16 h = __float2bfloat16(x);
    __nv_bfloat16 l = __float2bfloat16(x - __bfloat162float(h));
    hi = __bfloat16_as_ushort(h);
    lo = __bfloat16_as_ushort(l);
}
// pack two floats into (hi-pair, lo-pair) bf16x2 words
__device__ __forceinline__ void split_pack(float x, float y, uint32_t& hi, uint32_t& lo) {
    uint16_t hx, lx, hy, ly;
    split_bf16(x, hx, lx); split_bf16(y, hy, ly);
    hi = (uint32_t)hx | ((uint32_t)hy << 16);
    lo = (uint32_t)lx | ((uint32_t)ly << 16);
}

// ---------------------------------------------------------------------------
// Kernel 0: preconvert Q, K, V fp32 -> split bf16 hi/lo arrays.
// ---------------------------------------------------------------------------
__global__ void preconv(const float* __restrict__ Q, const float* __restrict__ K,
                        const float* __restrict__ V)
{
    const int n2 = NELEM / 2;
    uint32_t* qh = (uint32_t*)g_Qhi; uint32_t* ql = (uint32_t*)g_Qlo;
    uint32_t* kh = (uint32_t*)g_Khi; uint32_t* kl = (uint32_t*)g_Klo;
    uint32_t* vh = (uint32_t*)g_Vhi; uint32_t* vl = (uint32_t*)g_Vlo;
    for (int i = blockIdx.x * blockDim.x + threadIdx.x; i < n2;
         i += gridDim.x * blockDim.x) {
        float2 q = ((const float2*)Q)[i];
        float2 k = ((const float2*)K)[i];
        float2 v = ((const float2*)V)[i];
        split_pack(q.x, q.y, qh[i], ql[i]);
        split_pack(k.x, k.y, kh[i], kl[i]);
        split_pack(v.x, v.y, vh[i], vl[i]);
    }
}

// ---------------------------------------------------------------------------
// Kernel 1: raw scores + online softmax stats.
// CTA: 128 threads (4 warps, 2x2), 64 q x full 2048 k (16 tiles of 128).
// Warp tile: 32q x 64k. K tiles cp.async double-buffered. SMEM ~81 KB.
// ---------------------------------------------------------------------------
#define K1_QHI 0
#define K1_QLO 8192
#define K1_KHI 16384    // + buf*16384
#define K1_KLO 49152    // + buf*16384
#define K1_ST  81920    // stats combine: m[2][64], l[2][64]
#define K1_SMEM (81920 + 1024)

__global__ __launch_bounds__(128)
void scores_stats(const int* __restrict__ mask, float* __restrict__ attn)
{
    extern __shared__ char smem[];
    const uint32_t sb = smem_u32(smem);
    const int tid = threadIdx.x, wid = tid >> 5, lane = tid & 31;

    const int bh = blockIdx.y, b = bh >> 4;
    const int qBase = blockIdx.x * 64;

    // Q tile (resident): 64 rows x 128B, hi + lo
    const char* qhig = (const char*)(g_Qhi + (size_t)(bh * SEQ + qBase) * DKDIM);
    const char* qlog = (const char*)(g_Qlo + (size_t)(bh * SEQ + qBase) * DKDIM);
    #pragma unroll
    for (int i = tid; i < 512; i += 128) {
        const int r = i >> 3, c = i & 7;
        const uint32_t sw = SW128((uint32_t)(r * 128 + c * 16));
        CP16(sb + K1_QHI + sw, qhig + r * 128 + c * 16);
        CP16(sb + K1_QLO + sw, qlog + r * 128 + c * 16);
    }
    CP_COMMIT;

    const char* khig = (const char*)(g_Khi + (size_t)bh * SEQ * DKDIM);
    const char* klog = (const char*)(g_Klo + (size_t)bh * SEQ * DKDIM);

    auto issueK = [&](int kt, int buf) {
        #pragma unroll
        for (int i = tid; i < 1024; i += 128) {
            const int r = i >> 3, c = i & 7;
            const uint32_t sw = SW128((uint32_t)(r * 128 + c * 16));
            CP16(sb + K1_KHI + buf * 16384 + sw, khig + (size_t)(kt * 128 + r) * 128 + c * 16);
            CP16(sb + K1_KLO + buf * 16384 + sw, klog + (size_t)(kt * 128 + r) * 128 + c * 16);
        }
        CP_COMMIT;
    };
    issueK(0, 0);

    const int wy = wid >> 1, wx = wid & 1;
    const int wm = wy * 32;            // q offset within CTA
    const int wn = wx * 64;            // k offset within 128 tile
    const int arow = lane & 15;
    const int abyt = (lane >> 4) << 4;
    const int row0 = lane >> 2;

    float mst[2][2], lst[2][2];
    #pragma unroll
    for (int mi = 0; mi < 2; mi++) {
        mst[mi][0] = -INFINITY; mst[mi][1] = -INFINITY;
        lst[mi][0] = 0.0f;      lst[mi][1] = 0.0f;
    }

    const int* mp = mask + (size_t)b  * SEQ * SEQ;
    float*     ap = attn + (size_t)bh * SEQ * SEQ;

    for (int kt = 0; kt < 16; kt++) {
        if (kt + 1 < 16) { issueK(kt + 1, (kt + 1) & 1); CP_WAIT1; }
        else             { CP_WAIT0; }
        __syncthreads();

        const int buf = kt & 1;
        const uint32_t sqh = sb + K1_QHI, sql = sb + K1_QLO;
        const uint32_t skh = sb + K1_KHI + buf * 16384;
        const uint32_t skl = sb + K1_KLO + buf * 16384;

        float acc[2][8][4];
        #pragma unroll
        for (int mi = 0; mi < 2; mi++)
            #pragma unroll
            for (int nj = 0; nj < 8; nj++)
                #pragma unroll
                for (int e = 0; e < 4; e++) acc[mi][nj][e] = 0.0f;

        #pragma unroll
        for (int ks = 0; ks < 4; ks++) {
            uint32_t ah[2][4], al[2][4];
            #pragma unroll
            for (int mi = 0; mi < 2; mi++) {
                const uint32_t aoff = SW128((uint32_t)((wm + mi*16 + arow) * 128 + ks*32 + abyt));
                ldsm_x4(ah[mi], sqh + aoff);
                ldsm_x4(al[mi], sql + aoff);
            }
            #pragma unroll
            for (int nb = 0; nb < 4; nb++) {
                uint32_t bh4[4], bl4[4];
                const uint32_t boff = SW128((uint32_t)((wn + nb*16 + arow) * 128 + ks*32 + abyt));
                ldsm_x4(bh4, skh + boff);
                ldsm_x4(bl4, skl + boff);
                #pragma unroll
                for (int mi = 0; mi < 2; mi++) {
                    mma_bf16(acc[mi][nb*2],   ah[mi], bh4[0], bh4[2]);
                    mma_bf16(acc[mi][nb*2+1], ah[mi], bh4[1], bh4[3]);
                    mma_bf16(acc[mi][nb*2],   ah[mi], bl4[0], bl4[2]);
                    mma_bf16(acc[mi][nb*2+1], ah[mi], bl4[1], bl4[3]);
                    mma_bf16(acc[mi][nb*2],   al[mi], bh4[0], bh4[2]);
                    mma_bf16(acc[mi][nb*2+1], al[mi], bh4[1], bh4[3]);
                }
            }
        }

        // Mask + scale + store raw scores; update per-(mi,half) stats.
        #pragma unroll
        for (int mi = 0; mi < 2; mi++) {
            const int r0g = qBase + wm + mi * 16 + row0;
            float tmx0 = -INFINITY, tmx1 = -INFINITY;
            #pragma unroll
            for (int nj = 0; nj < 8; nj++) {
                const int col = kt * 128 + wn + nj * 8 + (lane & 3) * 2;
                const size_t o0 = (size_t)r0g * SEQ + col;
                const size_t o1 = o0 + (size_t)8 * SEQ;
                int2 ma = *(const int2*)&mp[o0];
                int2 mb = *(const int2*)&mp[o1];
                acc[mi][nj][0] = ma.x ? acc[mi][nj][0] * 0.125f : -1e9f;
                acc[mi][nj][1] = ma.y ? acc[mi][nj][1] * 0.125f : -1e9f;
                acc[mi][nj][2] = mb.x ? acc[mi][nj][2] * 0.125f : -1e9f;
                acc[mi][nj][3] = mb.y ? acc[mi][nj][3] * 0.125f : -1e9f;
                *(float2*)&ap[o0] = make_float2(acc[mi][nj][0], acc[mi][nj][1]);
                *(float2*)&ap[o1] = make_float2(acc[mi][nj][2], acc[mi][nj][3]);
                tmx0 = fmaxf(tmx0, fmaxf(acc[mi][nj][0], acc[mi][nj][1]));
                tmx1 = fmaxf(tmx1, fmaxf(acc[mi][nj][2], acc[mi][nj][3]));
            }
            tmx0 = fmaxf(tmx0, __shfl_xor_sync(0xffffffffu, tmx0, 1));
            tmx0 = fmaxf(tmx0, __shfl_xor_sync(0xffffffffu, tmx0, 2));
            tmx1 = fmaxf(tmx1, __shfl_xor_sync(0xffffffffu, tmx1, 1));
            tmx1 = fmaxf(tmx1, __shfl_xor_sync(0xffffffffu, tmx1, 2));

            const float m0n = fmaxf(mst[mi][0], tmx0);
            const float m1n = fmaxf(mst[mi][1], tmx1);
            float s0 = 0.0f, s1 = 0.0f;
            #pragma unroll
            for (int nj = 0; nj < 8; nj++) {
                s0 += __expf(acc[mi][nj][0] - m0n) + __expf(acc[mi][nj][1] - m0n);
                s1 += __expf(acc[mi][nj][2] - m1n) + __expf(acc[mi][nj][3] - m1n);
            }
            s0 += __shfl_xor_sync(0xffffffffu, s0, 1);
            s0 += __shfl_xor_sync(0xffffffffu, s0, 2);
            s1 += __shfl_xor_sync(0xffffffffu, s1, 1);
            s1 += __shfl_xor_sync(0xffffffffu, s1, 2);

            lst[mi][0] = lst[mi][0] * __expf(mst[mi][0] - m0n) + s0;  mst[mi][0] = m0n;
            lst[mi][1] = lst[mi][1] * __expf(mst[mi][1] - m1n) + s1;  mst[mi][1] = m1n;
        }
        __syncthreads();
    }

    // Combine (m,l) across the two wx warps sharing each row.
    float* smM = (float*)(smem + K1_ST);         // [2][64]
    float* smL = (float*)(smem + K1_ST + 512);   // [2][64]
    if ((lane & 3) == 0) {
        #pragma unroll
        for (int mi = 0; mi < 2; mi++) {
            const int rl = wm + mi * 16 + row0;
            smM[wx * 64 + rl]     = mst[mi][0];
            smM[wx * 64 + rl + 8] = mst[mi][1];
            smL[wx * 64 + rl]     = lst[mi][0];
            smL[wx * 64 + rl + 8] = lst[mi][1];
        }
    }
    __syncthreads();
    if (tid < 64) {
        const float ma = smM[tid], mb2 = smM[64 + tid];
        const float la = smL[tid], lb2 = smL[64 + tid];
        const float mf = fmaxf(ma, mb2);
        const float lf = la * __expf(ma - mf) + lb2 * __expf(mb2 - mf);
        g_M[(size_t)bh * SEQ + qBase + tid] = mf;
        g_L[(size_t)bh * SEQ + qBase + tid] = lf;
    }
}

// ---------------------------------------------------------------------------
// Kernel 2: normalize attn in place + out = P . V
// CTA: 128 threads, 64 q x 64 d; 32 k-tiles of 64. Warp = 16q x 64d.
// P loaded from raw scores DIRECTLY in MMA fragment layout (float2 LDG),
// exp'd + stored back, split to bf16 A-fragments in registers (no smem P).
// V tiles cp.async double-buffered. SMEM ~33 KB.
// ---------------------------------------------------------------------------
#define K2_VHI 0        // + buf*8192 (bufs 0, 8192)
#define K2_VLO 16384    // + buf*8192 (bufs 16384, 24576)
#define K2_M   32768
#define K2_IL  33024
#define K2_SMEM 33280

__global__ __launch_bounds__(128)
void out_norm(float* __restrict__ attn, float* __restrict__ out)
{
    extern __shared__ char smem[];
    const uint32_t sb = smem_u32(smem);
    const int tid = threadIdx.x, wid = tid >> 5, lane = tid & 31;

    const int bh = blockIdx.y;
    const int qBase = blockIdx.x * 64;

    float* ap = attn + (size_t)bh * SEQ * SEQ;

    float* sm_m  = (float*)(smem + K2_M);
    float* sm_il = (float*)(smem + K2_IL);
    if (tid < 64) {
        sm_m[tid]  = g_M[(size_t)bh * SEQ + qBase + tid];
        sm_il[tid] = 1.0f / g_L[(size_t)bh * SEQ + qBase + tid];
    }

    const char* vhig = (const char*)(g_Vhi + (size_t)bh * SEQ * DKDIM);
    const char* vlog = (const char*)(g_Vlo + (size_t)bh * SEQ * DKDIM);

    auto issueV = [&](int kt, int buf) {
        #pragma unroll
        for (int i = tid; i < 512; i += 128) {
            const int r = i >> 3, c = i & 7;
            const uint32_t sw = SW128((uint32_t)(r * 128 + c * 16));
            CP16(sb + K2_VHI + buf * 8192 + sw, vhig + (size_t)(kt * 64 + r) * 128 + c * 16);
            CP16(sb + K2_VLO + buf * 8192 + sw, vlog + (size_t)(kt * 64 + r) * 128 + c * 16);
        }
        CP_COMMIT;
    };
    issueV(0, 0);
    __syncthreads();   // sm_m/sm_il visible

    const int wm   = wid * 16;
    const int arow = lane & 15;
    const int abyt = (lane >> 4) << 4;
    const int row0 = lane >> 2;

    // Per-thread softmax stats for its two fixed rows.
    const float m0r  = sm_m[wm + row0],      m8r  = sm_m[wm + row0 + 8];
    const float il0r = sm_il[wm + row0],     il8r = sm_il[wm + row0 + 8];

    float acc[8][4];
    #pragma unroll
    for (int j = 0; j < 8; j++)
        #pragma unroll
        for (int e = 0; e < 4; e++) acc[j][e] = 0.0f;

    float* rowp0 = &ap[(size_t)(qBase + wm + row0) * SEQ + (lane & 3) * 2];
    float* rowp8 = rowp0 + (size_t)8 * SEQ;

    for (int kt = 0; kt < 32; kt++) {
        if (kt + 1 < 32) { issueV(kt + 1, (kt + 1) & 1); CP_WAIT1; }
        else             { CP_WAIT0; }
        __syncthreads();

        // Load S fragments (fragment layout), normalize, write attn, split.
        uint32_t pa_hi[4][4], pa_lo[4][4];   // A-fragments per k16 step
        #pragma unroll
        for (int nj = 0; nj < 8; nj++) {
            const int colb = kt * 64 + nj * 8;
            float2 s0 = *(const float2*)&rowp0[colb];
            float2 s1 = *(const float2*)&rowp8[colb];
            s0.x = __expf(s0.x - m0r) * il0r;
            s0.y = __expf(s0.y - m0r) * il0r;
            s1.x = __expf(s1.x - m8r) * il8r;
            s1.y = __expf(s1.y - m8r) * il8r;
            *(float2*)&rowp0[colb] = s0;
            *(float2*)&rowp8[colb] = s1;
            const int ks = nj >> 1, half = nj & 1;   // frag regs: half0 -> a0/a1, half1 -> a2/a3
            split_pack(s0.x, s0.y, pa_hi[ks][half*2],   pa_lo[ks][half*2]);
            split_pack(s1.x, s1.y, pa_hi[ks][half*2+1], pa_lo[ks][half*2+1]);
        }

        const int buf = kt & 1;
        const uint32_t svh = sb + K2_VHI + buf * 8192;
        const uint32_t svl = sb + K2_VLO + buf * 8192;

        #pragma unroll
        for (int ks = 0; ks < 4; ks++) {
            #pragma unroll
            for (int ng = 0; ng < 4; ng++) {
                uint32_t bh4[4], bl4[4];
                const uint32_t boff = SW128((uint32_t)((ks * 16 + arow) * 128 + ng * 32 + abyt));
                ldsm_x4_t(bh4, svh + boff);
                ldsm_x4_t(bl4, svl + boff);
                mma_bf16(acc[ng*2],   pa_hi[ks], bh4[0], bh4[1]);
                mma_bf16(acc[ng*2+1], pa_hi[ks], bh4[2], bh4[3]);
                mma_bf16(acc[ng*2],   pa_lo[ks], bh4[0], bh4[1]);
                mma_bf16(acc[ng*2+1], pa_lo[ks], bh4[2], bh4[3]);
                mma_bf16(acc[ng*2],   pa_hi[ks], bl4[0], bl4[1]);
                mma_bf16(acc[ng*2+1], pa_hi[ks], bl4[2], bl4[3]);
            }
        }
        __syncthreads();   // V buffer reuse protection
    }

    float* op = out + (size_t)bh * SEQ * DKDIM;
    const int r0 = qBase + wm + row0;
    #pragma unroll
    for (int j = 0; j < 8; j++) {
        const int col = j * 8 + (lane & 3) * 2;
        *(float2*)&op[(size_t)r0 * DKDIM + col]       = make_float2(acc[j][0], acc[j][1]);
        *(float2*)&op[(size_t)(r0 + 8) * DKDIM + col] = make_float2(acc[j][2], acc[j][3]);
    }
}

// ---------------------------------------------------------------------------
extern "C" void kernel_launch(void* const* d_in, const int* in_sizes, int n_in,
                              void* d_out, int out_size)
{
    const float* Q    = (const float*)d_in[0];
    const float* K    = (const float*)d_in[1];
    const float* V    = (const float*)d_in[2];
    const int*   mask = (const int*)  d_in[3];

    float* out  = (float*)d_out;
    float* attn = out + (size_t)BH * SEQ * DKDIM;

    cudaFuncSetAttribute(scores_stats, cudaFuncAttributeMaxDynamicSharedMemorySize, K1_SMEM);
    cudaFuncSetAttribute(out_norm,     cudaFuncAttributeMaxDynamicSharedMemorySize, K2_SMEM);

    preconv<<<2048, 256>>>(Q, K, V);
    scores_stats<<<dim3(SEQ / 64, BH), 128, K1_SMEM>>>(mask, attn);
    out_norm<<<dim3(SEQ / 64, BH), 128, K2_SMEM>>>(attn, out);
}

// round 8
// speedup vs baseline: 1.5814x; 1.5814x over previous
#include <cuda_runtime.h>
#include <cuda_bf16.h>
#include <cstdint>
#include <math.h>

#define BATCH 4
#define HEADS 16
#define SEQ   2048
#define DKDIM 64
#define BH    (BATCH*HEADS)
#define NELEM (BH*SEQ*DKDIM)   // 8,388,608

// Scratch (allowed: __device__ global arrays)
__device__ float g_M[BH * SEQ];
__device__ float g_L[BH * SEQ];
__device__ __nv_bfloat16 g_Qhi[NELEM], g_Qlo[NELEM];
__device__ __nv_bfloat16 g_Khi[NELEM], g_Klo[NELEM];
__device__ __nv_bfloat16 g_Vhi[NELEM], g_Vlo[NELEM];

// ---------------------------------------------------------------------------
// PTX helpers
// ---------------------------------------------------------------------------
__device__ __forceinline__ uint32_t smem_u32(const void* p) {
    uint32_t a;
    asm("{ .reg .u64 t; cvta.to.shared.u64 t, %1; cvt.u32.u64 %0, t; }"
        : "=r"(a) : "l"(p));
    return a;
}
__device__ __forceinline__ void ldsm_x4(uint32_t (&r)[4], uint32_t addr) {
    asm volatile("ldmatrix.sync.aligned.m8n8.x4.shared.b16 {%0,%1,%2,%3}, [%4];"
        : "=r"(r[0]), "=r"(r[1]), "=r"(r[2]), "=r"(r[3]) : "r"(addr));
}
__device__ __forceinline__ void ldsm_x4_t(uint32_t (&r)[4], uint32_t addr) {
    asm volatile("ldmatrix.sync.aligned.m8n8.x4.trans.shared.b16 {%0,%1,%2,%3}, [%4];"
        : "=r"(r[0]), "=r"(r[1]), "=r"(r[2]), "=r"(r[3]) : "r"(addr));
}
__device__ __forceinline__ void mma_bf16(float (&c)[4], const uint32_t (&a)[4],
                                         uint32_t b0, uint32_t b1) {
    asm volatile("mma.sync.aligned.m16n8k16.row.col.f32.bf16.bf16.f32 "
        "{%0,%1,%2,%3}, {%4,%5,%6,%7}, {%8,%9}, {%0,%1,%2,%3};"
        : "+f"(c[0]), "+f"(c[1]), "+f"(c[2]), "+f"(c[3])
        : "r"(a[0]), "r"(a[1]), "r"(a[2]), "r"(a[3]), "r"(b0), "r"(b1));
}
#define CP16(dst, src) \
    asm volatile("cp.async.cg.shared.global [%0], [%1], 16;" \
                 :: "r"(dst), "l"(src) : "memory")
#define CP_COMMIT  asm volatile("cp.async.commit_group;" ::: "memory")
#define CP_WAIT0   asm volatile("cp.async.wait_group 0;" ::: "memory")
#define CP_WAIT1   asm volatile("cp.async.wait_group 1;" ::: "memory")

#define SW128(b) ((b) ^ (((b) >> 3) & 0x70))

__device__ __forceinline__ void split_bf16(float x, uint16_t& hi, uint16_t& lo) {
    __nv_bfloat16 h = __float2bfloat16(x);
    __nv_bfloat16 l = __float2bfloat16(x - __bfloat162float(h));
    hi = __bfloat16_as_ushort(h);
    lo = __bfloat16_as_ushort(l);
}
__device__ __forceinline__ void split_pack(float x, float y, uint32_t& hi, uint32_t& lo) {
    uint16_t hx, lx, hy, ly;
    split_bf16(x, hx, lx); split_bf16(y, hy, ly);
    hi = (uint32_t)hx | ((uint32_t)hy << 16);
    lo = (uint32_t)lx | ((uint32_t)ly << 16);
}

// ---------------------------------------------------------------------------
// Kernel 0: preconvert Q, K, V fp32 -> split bf16 hi/lo arrays.
// ---------------------------------------------------------------------------
__global__ void preconv(const float* __restrict__ Q, const float* __restrict__ K,
                        const float* __restrict__ V)
{
    const int n2 = NELEM / 2;
    uint32_t* qh = (uint32_t*)g_Qhi; uint32_t* ql = (uint32_t*)g_Qlo;
    uint32_t* kh = (uint32_t*)g_Khi; uint32_t* kl = (uint32_t*)g_Klo;
    uint32_t* vh = (uint32_t*)g_Vhi; uint32_t* vl = (uint32_t*)g_Vlo;
    for (int i = blockIdx.x * blockDim.x + threadIdx.x; i < n2;
         i += gridDim.x * blockDim.x) {
        float2 q = ((const float2*)Q)[i];
        float2 k = ((const float2*)K)[i];
        float2 v = ((const float2*)V)[i];
        split_pack(q.x, q.y, qh[i], ql[i]);
        split_pack(k.x, k.y, kh[i], kl[i]);
        split_pack(v.x, v.y, vh[i], vl[i]);
    }
}

// ---------------------------------------------------------------------------
// Kernel 1: raw scores + online softmax stats.
// CTA: 128 threads (4 warps), 64 q rows x full 2048 k in 32 tiles of 64.
// Warp tile: 16q x 64k (warp owns full rows -> no cross-warp stats combine).
// K tiles cp.async double-buffered. SMEM 48 KB -> 4 CTAs/SM.
// ---------------------------------------------------------------------------
#define K1_QHI 0
#define K1_QLO 8192
#define K1_KB  16384    // stage s at 16384 + s*16384: [hi 8KB][lo 8KB]
#define K1_SMEM 49152

__global__ __launch_bounds__(128)
void scores_stats(const int* __restrict__ mask, float* __restrict__ attn)
{
    extern __shared__ char smem[];
    const uint32_t sb = smem_u32(smem);
    const int tid = threadIdx.x, wid = tid >> 5, lane = tid & 31;

    const int bh = blockIdx.y, b = bh >> 4;
    const int qBase = blockIdx.x * 64;

    // Q tile (resident): 64 rows x 128B, hi + lo
    const char* qhig = (const char*)(g_Qhi + (size_t)(bh * SEQ + qBase) * DKDIM);
    const char* qlog = (const char*)(g_Qlo + (size_t)(bh * SEQ + qBase) * DKDIM);
    #pragma unroll
    for (int i = tid; i < 512; i += 128) {
        const int r = i >> 3, c = i & 7;
        const uint32_t sw = SW128((uint32_t)(r * 128 + c * 16));
        CP16(sb + K1_QHI + sw, qhig + r * 128 + c * 16);
        CP16(sb + K1_QLO + sw, qlog + r * 128 + c * 16);
    }
    CP_COMMIT;

    const char* khig = (const char*)(g_Khi + (size_t)bh * SEQ * DKDIM);
    const char* klog = (const char*)(g_Klo + (size_t)bh * SEQ * DKDIM);

    // One K stage: 64 k-rows x 128B, hi + lo (16 KB)
    auto issueK = [&](int kt, int buf) {
        #pragma unroll
        for (int i = tid; i < 512; i += 128) {
            const int r = i >> 3, c = i & 7;
            const uint32_t sw = SW128((uint32_t)(r * 128 + c * 16));
            CP16(sb + K1_KB + buf * 16384 + sw,
                 khig + (size_t)(kt * 64 + r) * 128 + c * 16);
            CP16(sb + K1_KB + buf * 16384 + 8192 + sw,
                 klog + (size_t)(kt * 64 + r) * 128 + c * 16);
        }
        CP_COMMIT;
    };
    issueK(0, 0);

    const int wm   = wid * 16;
    const int arow = lane & 15;
    const int abyt = (lane >> 4) << 4;
    const int row0 = lane >> 2;

    float m0 = -INFINITY, m1 = -INFINITY, l0 = 0.0f, l1 = 0.0f;

    const int* mp = mask + (size_t)b  * SEQ * SEQ;
    float*     ap = attn + (size_t)bh * SEQ * SEQ;

    for (int kt = 0; kt < 32; kt++) {
        if (kt + 1 < 32) { issueK(kt + 1, (kt + 1) & 1); CP_WAIT1; }
        else             { CP_WAIT0; }
        __syncthreads();

        const int buf = kt & 1;
        const uint32_t sqh = sb + K1_QHI, sql = sb + K1_QLO;
        const uint32_t skh = sb + K1_KB + buf * 16384;
        const uint32_t skl = skh + 8192;

        float acc[8][4];
        #pragma unroll
        for (int j = 0; j < 8; j++)
            #pragma unroll
            for (int e = 0; e < 4; e++) acc[j][e] = 0.0f;

        #pragma unroll
        for (int ks = 0; ks < 4; ks++) {
            uint32_t ah[4], al[4];
            const uint32_t aoff = SW128((uint32_t)((wm + arow) * 128 + ks * 32 + abyt));
            ldsm_x4(ah, sqh + aoff);
            ldsm_x4(al, sql + aoff);
            #pragma unroll
            for (int nb = 0; nb < 4; nb++) {
                uint32_t bh4[4], bl4[4];
                const uint32_t boff = SW128((uint32_t)((nb * 16 + arow) * 128 + ks * 32 + abyt));
                ldsm_x4(bh4, skh + boff);
                ldsm_x4(bl4, skl + boff);
                mma_bf16(acc[nb*2],   ah, bh4[0], bh4[2]);
                mma_bf16(acc[nb*2+1], ah, bh4[1], bh4[3]);
                mma_bf16(acc[nb*2],   ah, bl4[0], bl4[2]);
                mma_bf16(acc[nb*2+1], ah, bl4[1], bl4[3]);
                mma_bf16(acc[nb*2],   al, bh4[0], bh4[2]);
                mma_bf16(acc[nb*2+1], al, bh4[1], bh4[3]);
            }
        }

        // Mask + scale + store raw scores; track tile max.
        const int r0g = qBase + wm + row0;
        float tmx0 = -INFINITY, tmx1 = -INFINITY;
        #pragma unroll
        for (int nj = 0; nj < 8; nj++) {
            const int col = kt * 64 + nj * 8 + (lane & 3) * 2;
            const size_t o0 = (size_t)r0g * SEQ + col;
            const size_t o1 = o0 + (size_t)8 * SEQ;
            int2 ma = *(const int2*)&mp[o0];
            int2 mb = *(const int2*)&mp[o1];
            acc[nj][0] = ma.x ? acc[nj][0] * 0.125f : -1e9f;
            acc[nj][1] = ma.y ? acc[nj][1] * 0.125f : -1e9f;
            acc[nj][2] = mb.x ? acc[nj][2] * 0.125f : -1e9f;
            acc[nj][3] = mb.y ? acc[nj][3] * 0.125f : -1e9f;
            *(float2*)&ap[o0] = make_float2(acc[nj][0], acc[nj][1]);
            *(float2*)&ap[o1] = make_float2(acc[nj][2], acc[nj][3]);
            tmx0 = fmaxf(tmx0, fmaxf(acc[nj][0], acc[nj][1]));
            tmx1 = fmaxf(tmx1, fmaxf(acc[nj][2], acc[nj][3]));
        }
        tmx0 = fmaxf(tmx0, __shfl_xor_sync(0xffffffffu, tmx0, 1));
        tmx0 = fmaxf(tmx0, __shfl_xor_sync(0xffffffffu, tmx0, 2));
        tmx1 = fmaxf(tmx1, __shfl_xor_sync(0xffffffffu, tmx1, 1));
        tmx1 = fmaxf(tmx1, __shfl_xor_sync(0xffffffffu, tmx1, 2));

        const float m0n = fmaxf(m0, tmx0);
        const float m1n = fmaxf(m1, tmx1);
        float s0 = 0.0f, s1 = 0.0f;
        #pragma unroll
        for (int nj = 0; nj < 8; nj++) {
            s0 += __expf(acc[nj][0] - m0n) + __expf(acc[nj][1] - m0n);
            s1 += __expf(acc[nj][2] - m1n) + __expf(acc[nj][3] - m1n);
        }
        s0 += __shfl_xor_sync(0xffffffffu, s0, 1);
        s0 += __shfl_xor_sync(0xffffffffu, s0, 2);
        s1 += __shfl_xor_sync(0xffffffffu, s1, 1);
        s1 += __shfl_xor_sync(0xffffffffu, s1, 2);

        l0 = l0 * __expf(m0 - m0n) + s0;  m0 = m0n;
        l1 = l1 * __expf(m1 - m1n) + s1;  m1 = m1n;

        __syncthreads();   // protect smem K buffer before reuse
    }

    if ((lane & 3) == 0) {
        const int r0g = qBase + wm + row0;
        g_M[(size_t)bh * SEQ + r0g]     = m0;
        g_L[(size_t)bh * SEQ + r0g]     = l0;
        g_M[(size_t)bh * SEQ + r0g + 8] = m1;
        g_L[(size_t)bh * SEQ + r0g + 8] = l1;
    }
}

// ---------------------------------------------------------------------------
// Kernel 2: normalize attn in place + out = P . V   (identical to round 5)
// CTA: 128 threads, 64 q x 64 d; 32 k-tiles of 64. Warp tile 16q x 64d.
// V tiles cp.async double-buffered from preconverted g_Vhi/g_Vlo. SMEM ~49 KB.
// ---------------------------------------------------------------------------
#define K2_PHI 0
#define K2_PLO 8192
#define K2_VHI 16384    // + buf*8192 (bufs 16384, 24576)
#define K2_VLO 32768    // + buf*8192 (bufs 32768, 40960)
#define K2_M   49152
#define K2_IL  49408
#define K2_SMEM 49664

__global__ __launch_bounds__(128)
void out_norm(float* __restrict__ attn, float* __restrict__ out)
{
    extern __shared__ char smem[];
    const uint32_t sb = smem_u32(smem);
    const int tid = threadIdx.x, wid = tid >> 5, lane = tid & 31;

    const int bh = blockIdx.y;
    const int qBase = blockIdx.x * 64;

    float* ap = attn + (size_t)bh * SEQ * SEQ;

    float* sm_m  = (float*)(smem + K2_M);
    float* sm_il = (float*)(smem + K2_IL);
    if (tid < 64) {
        sm_m[tid]  = g_M[(size_t)bh * SEQ + qBase + tid];
        sm_il[tid] = 1.0f / g_L[(size_t)bh * SEQ + qBase + tid];
    }

    const char* vhig = (const char*)(g_Vhi + (size_t)bh * SEQ * DKDIM);
    const char* vlog = (const char*)(g_Vlo + (size_t)bh * SEQ * DKDIM);

    auto issueV = [&](int kt, int buf) {
        #pragma unroll
        for (int i = tid; i < 512; i += 128) {
            const int r = i >> 3, c = i & 7;
            const uint32_t sw = SW128((uint32_t)(r * 128 + c * 16));
            CP16(sb + K2_VHI + buf * 8192 + sw, vhig + (size_t)(kt * 64 + r) * 128 + c * 16);
            CP16(sb + K2_VLO + buf * 8192 + sw, vlog + (size_t)(kt * 64 + r) * 128 + c * 16);
        }
        CP_COMMIT;
    };
    issueV(0, 0);
    __syncthreads();   // sm_m/sm_il visible

    const int wm   = wid * 16;
    const int arow = lane & 15;
    const int abyt = (lane >> 4) << 4;

    float acc[8][4];
    #pragma unroll
    for (int j = 0; j < 8; j++)
        #pragma unroll
        for (int e = 0; e < 4; e++) acc[j][e] = 0.0f;

    for (int kt = 0; kt < 32; kt++) {
        if (kt + 1 < 32) issueV(kt + 1, (kt + 1) & 1);

        // Normalize raw scores tile [64 x 64]: exp, write attn, split into smem.
        #pragma unroll
        for (int j = 0; j < 8; j++) {
            const int slot = tid + j * 128;          // 0..1023
            const int r = slot >> 4, c4 = slot & 15;
            float* row = &ap[(size_t)(qBase + r) * SEQ + kt * 64 + c4 * 4];
            float4 v = *(const float4*)row;
            const float mr = sm_m[r], il = sm_il[r];
            v.x = __expf(v.x - mr) * il;
            v.y = __expf(v.y - mr) * il;
            v.z = __expf(v.z - mr) * il;
            v.w = __expf(v.w - mr) * il;
            *(float4*)row = v;
            uint32_t h01, l01, h23, l23;
            split_pack(v.x, v.y, h01, l01);
            split_pack(v.z, v.w, h23, l23);
            const uint32_t sw = SW128((uint32_t)(r * 128 + c4 * 8));
            *(uint32_t*)(smem + K2_PHI + sw)     = h01;
            *(uint32_t*)(smem + K2_PHI + sw + 4) = h23;
            *(uint32_t*)(smem + K2_PLO + sw)     = l01;
            *(uint32_t*)(smem + K2_PLO + sw + 4) = l23;
        }

        if (kt + 1 < 32) { CP_WAIT1; } else { CP_WAIT0; }
        __syncthreads();

        const int buf = kt & 1;
        const uint32_t sph = sb + K2_PHI, spl = sb + K2_PLO;
        const uint32_t svh = sb + K2_VHI + buf * 8192;
        const uint32_t svl = sb + K2_VLO + buf * 8192;

        #pragma unroll
        for (int ks = 0; ks < 4; ks++) {
            uint32_t ah[4], al[4];
            const uint32_t aoff = SW128((uint32_t)((wm + arow) * 128 + ks * 32 + abyt));
            ldsm_x4(ah, sph + aoff);
            ldsm_x4(al, spl + aoff);
            #pragma unroll
            for (int ng = 0; ng < 4; ng++) {
                uint32_t bh4[4], bl4[4];
                const uint32_t boff = SW128((uint32_t)((ks * 16 + arow) * 128 + ng * 32 + abyt));
                ldsm_x4_t(bh4, svh + boff);
                ldsm_x4_t(bl4, svl + boff);
                mma_bf16(acc[ng*2],   ah, bh4[0], bh4[1]);
                mma_bf16(acc[ng*2+1], ah, bh4[2], bh4[3]);
                mma_bf16(acc[ng*2],   al, bh4[0], bh4[1]);
                mma_bf16(acc[ng*2+1], al, bh4[2], bh4[3]);
                mma_bf16(acc[ng*2],   ah, bl4[0], bl4[1]);
                mma_bf16(acc[ng*2+1], ah, bl4[2], bl4[3]);
            }
        }
        __syncthreads();   // P smem reused next iter
    }

    float* op = out + (size_t)bh * SEQ * DKDIM;
    const int r0 = qBase + wm + (lane >> 2);
    #pragma unroll
    for (int j = 0; j < 8; j++) {
        const int col = j * 8 + (lane & 3) * 2;
        *(float2*)&op[(size_t)r0 * DKDIM + col]       = make_float2(acc[j][0], acc[j][1]);
        *(float2*)&op[(size_t)(r0 + 8) * DKDIM + col] = make_float2(acc[j][2], acc[j][3]);
    }
}

// ---------------------------------------------------------------------------
extern "C" void kernel_launch(void* const* d_in, const int* in_sizes, int n_in,
                              void* d_out, int out_size)
{
    const float* Q    = (const float*)d_in[0];
    const float* K    = (const float*)d_in[1];
    const float* V    = (const float*)d_in[2];
    const int*   mask = (const int*)  d_in[3];

    float* out  = (float*)d_out;
    float* attn = out + (size_t)BH * SEQ * DKDIM;

    cudaFuncSetAttribute(scores_stats, cudaFuncAttributeMaxDynamicSharedMemorySize, K1_SMEM);
    cudaFuncSetAttribute(out_norm,     cudaFuncAttributeMaxDynamicSharedMemorySize, K2_SMEM);

    preconv<<<2048, 256>>>(Q, K, V);
    scores_stats<<<dim3(SEQ / 64, BH), 128, K1_SMEM>>>(mask, attn);
    out_norm<<<dim3(SEQ / 64, BH), 128, K2_SMEM>>>(attn, out);
}

// round 9
// speedup vs baseline: 1.9767x; 1.2499x over previous
#include <cuda_runtime.h>
#include <cuda_bf16.h>
#include <cstdint>
#include <math.h>

#define BATCH 4
#define HEADS 16
#define SEQ   2048
#define DKDIM 64
#define BH    (BATCH*HEADS)
#define NELEM (BH*SEQ*DKDIM)   // 8,388,608

// Scratch (allowed: __device__ global arrays)
__device__ float g_M[BH * SEQ];
__device__ float g_L[BH * SEQ];
__device__ __nv_bfloat16 g_Qhi[NELEM], g_Qlo[NELEM];
__device__ __nv_bfloat16 g_Khi[NELEM], g_Klo[NELEM];
__device__ __nv_bfloat16 g_Vhi[NELEM], g_Vlo[NELEM];

// ---------------------------------------------------------------------------
// PTX helpers
// ---------------------------------------------------------------------------
__device__ __forceinline__ uint32_t smem_u32(const void* p) {
    uint32_t a;
    asm("{ .reg .u64 t; cvta.to.shared.u64 t, %1; cvt.u32.u64 %0, t; }"
        : "=r"(a) : "l"(p));
    return a;
}
__device__ __forceinline__ void ldsm_x4(uint32_t (&r)[4], uint32_t addr) {
    asm volatile("ldmatrix.sync.aligned.m8n8.x4.shared.b16 {%0,%1,%2,%3}, [%4];"
        : "=r"(r[0]), "=r"(r[1]), "=r"(r[2]), "=r"(r[3]) : "r"(addr));
}
__device__ __forceinline__ void ldsm_x4_t(uint32_t (&r)[4], uint32_t addr) {
    asm volatile("ldmatrix.sync.aligned.m8n8.x4.trans.shared.b16 {%0,%1,%2,%3}, [%4];"
        : "=r"(r[0]), "=r"(r[1]), "=r"(r[2]), "=r"(r[3]) : "r"(addr));
}
__device__ __forceinline__ void mma_bf16(float (&c)[4], const uint32_t (&a)[4],
                                         uint32_t b0, uint32_t b1) {
    asm volatile("mma.sync.aligned.m16n8k16.row.col.f32.bf16.bf16.f32 "
        "{%0,%1,%2,%3}, {%4,%5,%6,%7}, {%8,%9}, {%0,%1,%2,%3};"
        : "+f"(c[0]), "+f"(c[1]), "+f"(c[2]), "+f"(c[3])
        : "r"(a[0]), "r"(a[1]), "r"(a[2]), "r"(a[3]), "r"(b0), "r"(b1));
}
#define CP16(dst, src) \
    asm volatile("cp.async.cg.shared.global [%0], [%1], 16;" \
                 :: "r"(dst), "l"(src) : "memory")
#define CP_COMMIT  asm volatile("cp.async.commit_group;" ::: "memory")
#define CP_WAIT0   asm volatile("cp.async.wait_group 0;" ::: "memory")
#define CP_WAIT1   asm volatile("cp.async.wait_group 1;" ::: "memory")
#define CP_WAIT2   asm volatile("cp.async.wait_group 2;" ::: "memory")

#define SW128(b) ((b) ^ (((b) >> 3) & 0x70))

__device__ __forceinline__ void split_bf16(float x, uint16_t& hi, uint16_t& lo) {
    __nv_bfloat16 h = __float2bfloat16(x);
    __nv_bfloat16 l = __float2bfloat16(x - __bfloat162float(h));
    hi = __bfloat16_as_ushort(h);
    lo = __bfloat16_as_ushort(l);
}
__device__ __forceinline__ void split_pack(float x, float y, uint32_t& hi, uint32_t& lo) {
    uint16_t hx, lx, hy, ly;
    split_bf16(x, hx, lx); split_bf16(y, hy, ly);
    hi = (uint32_t)hx | ((uint32_t)hy << 16);
    lo = (uint32_t)lx | ((uint32_t)ly << 16);
}

// ---------------------------------------------------------------------------
// Kernel 0: preconvert Q, K, V fp32 -> split bf16 hi/lo arrays.
// ---------------------------------------------------------------------------
__global__ void preconv(const float* __restrict__ Q, const float* __restrict__ K,
                        const float* __restrict__ V)
{
    const int n2 = NELEM / 2;
    uint32_t* qh = (uint32_t*)g_Qhi; uint32_t* ql = (uint32_t*)g_Qlo;
    uint32_t* kh = (uint32_t*)g_Khi; uint32_t* kl = (uint32_t*)g_Klo;
    uint32_t* vh = (uint32_t*)g_Vhi; uint32_t* vl = (uint32_t*)g_Vlo;
    for (int i = blockIdx.x * blockDim.x + threadIdx.x; i < n2;
         i += gridDim.x * blockDim.x) {
        float2 q = ((const float2*)Q)[i];
        float2 k = ((const float2*)K)[i];
        float2 v = ((const float2*)V)[i];
        split_pack(q.x, q.y, qh[i], ql[i]);
        split_pack(k.x, k.y, kh[i], kl[i]);
        split_pack(v.x, v.y, vh[i], vl[i]);
    }
}

// ---------------------------------------------------------------------------
// Kernel A: softmax stats only (no score stores).
// CTA: 128 threads (4 warps), 64 q rows x full 2048 k in 32 tiles of 64.
// Warp tile: 16q x 64k. K tiles cp.async double-buffered. SMEM 48 KB.
// ---------------------------------------------------------------------------
#define K1_QHI 0
#define K1_QLO 8192
#define K1_KB  16384
#define K1_SMEM 49152

__global__ __launch_bounds__(128)
void stats_pass(const int* __restrict__ mask)
{
    extern __shared__ char smem[];
    const uint32_t sb = smem_u32(smem);
    const int tid = threadIdx.x, wid = tid >> 5, lane = tid & 31;

    const int bh = blockIdx.y, b = bh >> 4;
    const int qBase = blockIdx.x * 64;

    const char* qhig = (const char*)(g_Qhi + (size_t)(bh * SEQ + qBase) * DKDIM);
    const char* qlog = (const char*)(g_Qlo + (size_t)(bh * SEQ + qBase) * DKDIM);
    #pragma unroll
    for (int i = tid; i < 512; i += 128) {
        const int r = i >> 3, c = i & 7;
        const uint32_t sw = SW128((uint32_t)(r * 128 + c * 16));
        CP16(sb + K1_QHI + sw, qhig + r * 128 + c * 16);
        CP16(sb + K1_QLO + sw, qlog + r * 128 + c * 16);
    }
    CP_COMMIT;

    const char* khig = (const char*)(g_Khi + (size_t)bh * SEQ * DKDIM);
    const char* klog = (const char*)(g_Klo + (size_t)bh * SEQ * DKDIM);

    auto issueK = [&](int kt, int buf) {
        #pragma unroll
        for (int i = tid; i < 512; i += 128) {
            const int r = i >> 3, c = i & 7;
            const uint32_t sw = SW128((uint32_t)(r * 128 + c * 16));
            CP16(sb + K1_KB + buf * 16384 + sw,
                 khig + (size_t)(kt * 64 + r) * 128 + c * 16);
            CP16(sb + K1_KB + buf * 16384 + 8192 + sw,
                 klog + (size_t)(kt * 64 + r) * 128 + c * 16);
        }
        CP_COMMIT;
    };
    issueK(0, 0);

    const int wm   = wid * 16;
    const int arow = lane & 15;
    const int abyt = (lane >> 4) << 4;
    const int row0 = lane >> 2;

    float m0 = -INFINITY, m1 = -INFINITY, l0 = 0.0f, l1 = 0.0f;

    const int* mp = mask + (size_t)b * SEQ * SEQ;

    for (int kt = 0; kt < 32; kt++) {
        if (kt + 1 < 32) { issueK(kt + 1, (kt + 1) & 1); CP_WAIT1; }
        else             { CP_WAIT0; }
        __syncthreads();

        const int buf = kt & 1;
        const uint32_t sqh = sb + K1_QHI, sql = sb + K1_QLO;
        const uint32_t skh = sb + K1_KB + buf * 16384;
        const uint32_t skl = skh + 8192;

        float acc[8][4];
        #pragma unroll
        for (int j = 0; j < 8; j++)
            #pragma unroll
            for (int e = 0; e < 4; e++) acc[j][e] = 0.0f;

        #pragma unroll
        for (int ks = 0; ks < 4; ks++) {
            uint32_t ah[4], al[4];
            const uint32_t aoff = SW128((uint32_t)((wm + arow) * 128 + ks * 32 + abyt));
            ldsm_x4(ah, sqh + aoff);
            ldsm_x4(al, sql + aoff);
            #pragma unroll
            for (int nb = 0; nb < 4; nb++) {
                uint32_t bh4[4], bl4[4];
                const uint32_t boff = SW128((uint32_t)((nb * 16 + arow) * 128 + ks * 32 + abyt));
                ldsm_x4(bh4, skh + boff);
                ldsm_x4(bl4, skl + boff);
                mma_bf16(acc[nb*2],   ah, bh4[0], bh4[2]);
                mma_bf16(acc[nb*2+1], ah, bh4[1], bh4[3]);
                mma_bf16(acc[nb*2],   ah, bl4[0], bl4[2]);
                mma_bf16(acc[nb*2+1], ah, bl4[1], bl4[3]);
                mma_bf16(acc[nb*2],   al, bh4[0], bh4[2]);
                mma_bf16(acc[nb*2+1], al, bh4[1], bh4[3]);
            }
        }

        // Mask + scale; track tile max and exp-sum (no stores).
        const int r0g = qBase + wm + row0;
        float tmx0 = -INFINITY, tmx1 = -INFINITY;
        #pragma unroll
        for (int nj = 0; nj < 8; nj++) {
            const int col = kt * 64 + nj * 8 + (lane & 3) * 2;
            const size_t o0 = (size_t)r0g * SEQ + col;
            const size_t o1 = o0 + (size_t)8 * SEQ;
            int2 ma = *(const int2*)&mp[o0];
            int2 mb = *(const int2*)&mp[o1];
            acc[nj][0] = ma.x ? acc[nj][0] * 0.125f : -1e9f;
            acc[nj][1] = ma.y ? acc[nj][1] * 0.125f : -1e9f;
            acc[nj][2] = mb.x ? acc[nj][2] * 0.125f : -1e9f;
            acc[nj][3] = mb.y ? acc[nj][3] * 0.125f : -1e9f;
            tmx0 = fmaxf(tmx0, fmaxf(acc[nj][0], acc[nj][1]));
            tmx1 = fmaxf(tmx1, fmaxf(acc[nj][2], acc[nj][3]));
        }
        tmx0 = fmaxf(tmx0, __shfl_xor_sync(0xffffffffu, tmx0, 1));
        tmx0 = fmaxf(tmx0, __shfl_xor_sync(0xffffffffu, tmx0, 2));
        tmx1 = fmaxf(tmx1, __shfl_xor_sync(0xffffffffu, tmx1, 1));
        tmx1 = fmaxf(tmx1, __shfl_xor_sync(0xffffffffu, tmx1, 2));

        const float m0n = fmaxf(m0, tmx0);
        const float m1n = fmaxf(m1, tmx1);
        float s0 = 0.0f, s1 = 0.0f;
        #pragma unroll
        for (int nj = 0; nj < 8; nj++) {
            s0 += __expf(acc[nj][0] - m0n) + __expf(acc[nj][1] - m0n);
            s1 += __expf(acc[nj][2] - m1n) + __expf(acc[nj][3] - m1n);
        }
        s0 += __shfl_xor_sync(0xffffffffu, s0, 1);
        s0 += __shfl_xor_sync(0xffffffffu, s0, 2);
        s1 += __shfl_xor_sync(0xffffffffu, s1, 1);
        s1 += __shfl_xor_sync(0xffffffffu, s1, 2);

        l0 = l0 * __expf(m0 - m0n) + s0;  m0 = m0n;
        l1 = l1 * __expf(m1 - m1n) + s1;  m1 = m1n;

        __syncthreads();
    }

    if ((lane & 3) == 0) {
        const int r0g = qBase + wm + row0;
        g_M[(size_t)bh * SEQ + r0g]     = m0;
        g_L[(size_t)bh * SEQ + r0g]     = l0;
        g_M[(size_t)bh * SEQ + r0g + 8] = m1;
        g_L[(size_t)bh * SEQ + r0g + 8] = l1;
    }
}

// ---------------------------------------------------------------------------
// Kernel B: recompute QK^T, normalize with (m,l), write attn once, and
// accumulate out = P . V with P fragments built in registers.
// CTA: 128 threads, 64 q x 64 d; 32 k-tiles of 64. Warp = 16q (full rows).
// K double-buffered; V single-staged (issued early, used after QK phase).
// SMEM 66 KB -> 3 CTAs/SM.
// ---------------------------------------------------------------------------
#define B_QHI 0
#define B_QLO 8192
#define B_KB  16384    // stage buf*16384: [hi 8KB][lo 8KB]
#define B_VHI 49152
#define B_VLO 57344
#define B_M   65536
#define B_IL  65792
#define B_SMEM 66048

__global__ __launch_bounds__(128, 3)
void recompute_pv(const int* __restrict__ mask, float* __restrict__ attn,
                  float* __restrict__ out)
{
    extern __shared__ char smem[];
    const uint32_t sb = smem_u32(smem);
    const int tid = threadIdx.x, wid = tid >> 5, lane = tid & 31;

    const int bh = blockIdx.y, b = bh >> 4;
    const int qBase = blockIdx.x * 64;

    float* sm_m  = (float*)(smem + B_M);
    float* sm_il = (float*)(smem + B_IL);
    if (tid < 64) {
        sm_m[tid]  = g_M[(size_t)bh * SEQ + qBase + tid];
        sm_il[tid] = 1.0f / g_L[(size_t)bh * SEQ + qBase + tid];
    }

    const char* qhig = (const char*)(g_Qhi + (size_t)(bh * SEQ + qBase) * DKDIM);
    const char* qlog = (const char*)(g_Qlo + (size_t)(bh * SEQ + qBase) * DKDIM);
    #pragma unroll
    for (int i = tid; i < 512; i += 128) {
        const int r = i >> 3, c = i & 7;
        const uint32_t sw = SW128((uint32_t)(r * 128 + c * 16));
        CP16(sb + B_QHI + sw, qhig + r * 128 + c * 16);
        CP16(sb + B_QLO + sw, qlog + r * 128 + c * 16);
    }
    CP_COMMIT;

    const char* khig = (const char*)(g_Khi + (size_t)bh * SEQ * DKDIM);
    const char* klog = (const char*)(g_Klo + (size_t)bh * SEQ * DKDIM);
    const char* vhig = (const char*)(g_Vhi + (size_t)bh * SEQ * DKDIM);
    const char* vlog = (const char*)(g_Vlo + (size_t)bh * SEQ * DKDIM);

    auto issueK = [&](int kt, int buf) {
        #pragma unroll
        for (int i = tid; i < 512; i += 128) {
            const int r = i >> 3, c = i & 7;
            const uint32_t sw = SW128((uint32_t)(r * 128 + c * 16));
            CP16(sb + B_KB + buf * 16384 + sw,
                 khig + (size_t)(kt * 64 + r) * 128 + c * 16);
            CP16(sb + B_KB + buf * 16384 + 8192 + sw,
                 klog + (size_t)(kt * 64 + r) * 128 + c * 16);
        }
        CP_COMMIT;
    };
    auto issueV = [&](int kt) {
        #pragma unroll
        for (int i = tid; i < 512; i += 128) {
            const int r = i >> 3, c = i & 7;
            const uint32_t sw = SW128((uint32_t)(r * 128 + c * 16));
            CP16(sb + B_VHI + sw, vhig + (size_t)(kt * 64 + r) * 128 + c * 16);
            CP16(sb + B_VLO + sw, vlog + (size_t)(kt * 64 + r) * 128 + c * 16);
        }
        CP_COMMIT;
    };
    issueK(0, 0);
    __syncthreads();   // sm_m/sm_il visible

    const int wm   = wid * 16;
    const int arow = lane & 15;
    const int abyt = (lane >> 4) << 4;
    const int row0 = lane >> 2;

    const float m0r  = sm_m[wm + row0],  m8r  = sm_m[wm + row0 + 8];
    const float il0r = sm_il[wm + row0], il8r = sm_il[wm + row0 + 8];

    const int* mp = mask + (size_t)b  * SEQ * SEQ;
    float*     ap = attn + (size_t)bh * SEQ * SEQ;

    float oacc[8][4];
    #pragma unroll
    for (int j = 0; j < 8; j++)
        #pragma unroll
        for (int e = 0; e < 4; e++) oacc[j][e] = 0.0f;

    for (int kt = 0; kt < 32; kt++) {
        if (kt + 1 < 32) issueK(kt + 1, (kt + 1) & 1);
        issueV(kt);
        // Wait for K(kt): newer pending groups = K(kt+1) (if any) + V(kt).
        if (kt + 1 < 32) { CP_WAIT2; } else { CP_WAIT1; }
        __syncthreads();

        const int buf = kt & 1;
        const uint32_t sqh = sb + B_QHI, sql = sb + B_QLO;
        const uint32_t skh = sb + B_KB + buf * 16384;
        const uint32_t skl = skh + 8192;

        // ---- QK^T (3-term split) ----
        float acc[8][4];
        #pragma unroll
        for (int j = 0; j < 8; j++)
            #pragma unroll
            for (int e = 0; e < 4; e++) acc[j][e] = 0.0f;

        #pragma unroll
        for (int ks = 0; ks < 4; ks++) {
            uint32_t ah[4], al[4];
            const uint32_t aoff = SW128((uint32_t)((wm + arow) * 128 + ks * 32 + abyt));
            ldsm_x4(ah, sqh + aoff);
            ldsm_x4(al, sql + aoff);
            #pragma unroll
            for (int nb = 0; nb < 4; nb++) {
                uint32_t bh4[4], bl4[4];
                const uint32_t boff = SW128((uint32_t)((nb * 16 + arow) * 128 + ks * 32 + abyt));
                ldsm_x4(bh4, skh + boff);
                ldsm_x4(bl4, skl + boff);
                mma_bf16(acc[nb*2],   ah, bh4[0], bh4[2]);
                mma_bf16(acc[nb*2+1], ah, bh4[1], bh4[3]);
                mma_bf16(acc[nb*2],   ah, bl4[0], bl4[2]);
                mma_bf16(acc[nb*2+1], ah, bl4[1], bl4[3]);
                mma_bf16(acc[nb*2],   al, bh4[0], bh4[2]);
                mma_bf16(acc[nb*2+1], al, bh4[1], bh4[3]);
            }
        }

        // ---- mask + normalize + write attn + build P A-fragments ----
        uint32_t pa_hi[4][4], pa_lo[4][4];
        const int r0g = qBase + wm + row0;
        #pragma unroll
        for (int nj = 0; nj < 8; nj++) {
            const int col = kt * 64 + nj * 8 + (lane & 3) * 2;
            const size_t o0 = (size_t)r0g * SEQ + col;
            const size_t o1 = o0 + (size_t)8 * SEQ;
            int2 ma = *(const int2*)&mp[o0];
            int2 mb = *(const int2*)&mp[o1];
            float2 p0, p1;
            p0.x = __expf((ma.x ? acc[nj][0] * 0.125f : -1e9f) - m0r) * il0r;
            p0.y = __expf((ma.y ? acc[nj][1] * 0.125f : -1e9f) - m0r) * il0r;
            p1.x = __expf((mb.x ? acc[nj][2] * 0.125f : -1e9f) - m8r) * il8r;
            p1.y = __expf((mb.y ? acc[nj][3] * 0.125f : -1e9f) - m8r) * il8r;
            *(float2*)&ap[o0] = p0;
            *(float2*)&ap[o1] = p1;
            const int ks = nj >> 1, half = nj & 1;
            split_pack(p0.x, p0.y, pa_hi[ks][half*2],   pa_lo[ks][half*2]);
            split_pack(p1.x, p1.y, pa_hi[ks][half*2+1], pa_lo[ks][half*2+1]);
        }

        // ---- P . V ----
        CP_WAIT0;
        __syncthreads();
        const uint32_t svh = sb + B_VHI, svl = sb + B_VLO;
        #pragma unroll
        for (int ks = 0; ks < 4; ks++) {
            #pragma unroll
            for (int ng = 0; ng < 4; ng++) {
                uint32_t bh4[4], bl4[4];
                const uint32_t boff = SW128((uint32_t)((ks * 16 + arow) * 128 + ng * 32 + abyt));
                ldsm_x4_t(bh4, svh + boff);
                ldsm_x4_t(bl4, svl + boff);
                mma_bf16(oacc[ng*2],   pa_hi[ks], bh4[0], bh4[1]);
                mma_bf16(oacc[ng*2+1], pa_hi[ks], bh4[2], bh4[3]);
                mma_bf16(oacc[ng*2],   pa_lo[ks], bh4[0], bh4[1]);
                mma_bf16(oacc[ng*2+1], pa_lo[ks], bh4[2], bh4[3]);
                mma_bf16(oacc[ng*2],   pa_hi[ks], bl4[0], bl4[1]);
                mma_bf16(oacc[ng*2+1], pa_hi[ks], bl4[2], bl4[3]);
            }
        }
        __syncthreads();   // protect V stage + K buf before next iteration
    }

    float* op = out + (size_t)bh * SEQ * DKDIM;
    const int r0 = qBase + wm + row0;
    #pragma unroll
    for (int j = 0; j < 8; j++) {
        const int col = j * 8 + (lane & 3) * 2;
        *(float2*)&op[(size_t)r0 * DKDIM + col]       = make_float2(oacc[j][0], oacc[j][1]);
        *(float2*)&op[(size_t)(r0 + 8) * DKDIM + col] = make_float2(oacc[j][2], oacc[j][3]);
    }
}

// ---------------------------------------------------------------------------
extern "C" void kernel_launch(void* const* d_in, const int* in_sizes, int n_in,
                              void* d_out, int out_size)
{
    const float* Q    = (const float*)d_in[0];
    const float* K    = (const float*)d_in[1];
    const float* V    = (const float*)d_in[2];
    const int*   mask = (const int*)  d_in[3];

    float* out  = (float*)d_out;
    float* attn = out + (size_t)BH * SEQ * DKDIM;

    cudaFuncSetAttribute(stats_pass,   cudaFuncAttributeMaxDynamicSharedMemorySize, K1_SMEM);
    cudaFuncSetAttribute(recompute_pv, cudaFuncAttributeMaxDynamicSharedMemorySize, B_SMEM);

    preconv<<<2048, 256>>>(Q, K, V);
    stats_pass<<<dim3(SEQ / 64, BH), 128, K1_SMEM>>>(mask);
    recompute_pv<<<dim3(SEQ / 64, BH), 128, B_SMEM>>>(mask, attn, out);
}

// round 10
// speedup vs baseline: 2.8504x; 1.4420x over previous
#include <cuda_runtime.h>
#include <cuda_fp16.h>
#include <cstdint>
#include <math.h>

#define BATCH 4
#define HEADS 16
#define SEQ   2048
#define DKDIM 64
#define BH    (BATCH*HEADS)
#define NELEM (BH*SEQ*DKDIM)   // 8,388,608

// Scratch (allowed: __device__ global arrays)
__device__ float g_M[BH * SEQ];
__device__ float g_L[BH * SEQ];
__device__ __half g_Qh[NELEM], g_Ql[NELEM];   // Q split hi/lo fp16
__device__ __half g_Kh[NELEM];                // K single fp16
__device__ __half g_Vh[NELEM];                // V single fp16

// ---------------------------------------------------------------------------
// PTX helpers
// ---------------------------------------------------------------------------
__device__ __forceinline__ uint32_t smem_u32(const void* p) {
    uint32_t a;
    asm("{ .reg .u64 t; cvta.to.shared.u64 t, %1; cvt.u32.u64 %0, t; }"
        : "=r"(a) : "l"(p));
    return a;
}
__device__ __forceinline__ void ldsm_x4(uint32_t (&r)[4], uint32_t addr) {
    asm volatile("ldmatrix.sync.aligned.m8n8.x4.shared.b16 {%0,%1,%2,%3}, [%4];"
        : "=r"(r[0]), "=r"(r[1]), "=r"(r[2]), "=r"(r[3]) : "r"(addr));
}
__device__ __forceinline__ void ldsm_x4_t(uint32_t (&r)[4], uint32_t addr) {
    asm volatile("ldmatrix.sync.aligned.m8n8.x4.trans.shared.b16 {%0,%1,%2,%3}, [%4];"
        : "=r"(r[0]), "=r"(r[1]), "=r"(r[2]), "=r"(r[3]) : "r"(addr));
}
__device__ __forceinline__ void mma_f16(float (&c)[4], const uint32_t (&a)[4],
                                        uint32_t b0, uint32_t b1) {
    asm volatile("mma.sync.aligned.m16n8k16.row.col.f32.f16.f16.f32 "
        "{%0,%1,%2,%3}, {%4,%5,%6,%7}, {%8,%9}, {%0,%1,%2,%3};"
        : "+f"(c[0]), "+f"(c[1]), "+f"(c[2]), "+f"(c[3])
        : "r"(a[0]), "r"(a[1]), "r"(a[2]), "r"(a[3]), "r"(b0), "r"(b1));
}
#define CP16(dst, src) \
    asm volatile("cp.async.cg.shared.global [%0], [%1], 16;" \
                 :: "r"(dst), "l"(src) : "memory")
#define CP_COMMIT  asm volatile("cp.async.commit_group;" ::: "memory")
#define CP_WAIT0   asm volatile("cp.async.wait_group 0;" ::: "memory")
#define CP_WAIT1   asm volatile("cp.async.wait_group 1;" ::: "memory")
#define CP_WAIT2   asm volatile("cp.async.wait_group 2;" ::: "memory")

#define SW128(b) ((b) ^ (((b) >> 3) & 0x70))

__device__ __forceinline__ uint32_t pack_h2(float x, float y) {
    __half2 h = __floats2half2_rn(x, y);
    return *reinterpret_cast<uint32_t*>(&h);
}
// fp16 split of a float pair -> (hi-pair, lo-pair) words
__device__ __forceinline__ void splith2(float x, float y, uint32_t& hi, uint32_t& lo) {
    __half2 h = __floats2half2_rn(x, y);
    hi = *reinterpret_cast<uint32_t*>(&h);
    lo = pack_h2(x - __low2float(h), y - __high2float(h));
}

// ---------------------------------------------------------------------------
// Kernel 0: preconvert. Q -> fp16 hi/lo, K -> fp16, V -> fp16.
// ---------------------------------------------------------------------------
__global__ void preconv(const float* __restrict__ Q, const float* __restrict__ K,
                        const float* __restrict__ V)
{
    const int n2 = NELEM / 2;
    uint32_t* qh = (uint32_t*)g_Qh; uint32_t* ql = (uint32_t*)g_Ql;
    uint32_t* kh = (uint32_t*)g_Kh; uint32_t* vh = (uint32_t*)g_Vh;
    for (int i = blockIdx.x * blockDim.x + threadIdx.x; i < n2;
         i += gridDim.x * blockDim.x) {
        float2 q = ((const float2*)Q)[i];
        float2 k = ((const float2*)K)[i];
        float2 v = ((const float2*)V)[i];
        splith2(q.x, q.y, qh[i], ql[i]);
        kh[i] = pack_h2(k.x, k.y);
        vh[i] = pack_h2(v.x, v.y);
    }
}

// ---------------------------------------------------------------------------
// Kernel A: softmax stats only. 1-term fp16 QK^T (Qh . Kh).
// CTA: 128 threads (4 warps), 64 q x 2048 k in 32 tiles of 64.
// Warp tile: 16q x 64k. K double-buffered. SMEM 24 KB.
// ---------------------------------------------------------------------------
#define S_Q  0
#define S_KB 8192    // stage buf at 8192 + buf*8192
#define S_SMEM 24576

__global__ __launch_bounds__(128)
void stats_pass(const int* __restrict__ mask)
{
    extern __shared__ char smem[];
    const uint32_t sb = smem_u32(smem);
    const int tid = threadIdx.x, wid = tid >> 5, lane = tid & 31;

    const int bh = blockIdx.y, b = bh >> 4;
    const int qBase = blockIdx.x * 64;

    const char* qhg = (const char*)(g_Qh + (size_t)(bh * SEQ + qBase) * DKDIM);
    #pragma unroll
    for (int i = tid; i < 512; i += 128) {
        const int r = i >> 3, c = i & 7;
        CP16(sb + S_Q + SW128((uint32_t)(r * 128 + c * 16)), qhg + r * 128 + c * 16);
    }
    CP_COMMIT;

    const char* khg = (const char*)(g_Kh + (size_t)bh * SEQ * DKDIM);
    auto issueK = [&](int kt, int buf) {
        #pragma unroll
        for (int i = tid; i < 512; i += 128) {
            const int r = i >> 3, c = i & 7;
            CP16(sb + S_KB + buf * 8192 + SW128((uint32_t)(r * 128 + c * 16)),
                 khg + (size_t)(kt * 64 + r) * 128 + c * 16);
        }
        CP_COMMIT;
    };
    issueK(0, 0);

    const int wm   = wid * 16;
    const int arow = lane & 15;
    const int abyt = (lane >> 4) << 4;
    const int row0 = lane >> 2;

    float m0 = -INFINITY, m1 = -INFINITY, l0 = 0.0f, l1 = 0.0f;
    const int* mp = mask + (size_t)b * SEQ * SEQ;

    for (int kt = 0; kt < 32; kt++) {
        if (kt + 1 < 32) { issueK(kt + 1, (kt + 1) & 1); CP_WAIT1; }
        else             { CP_WAIT0; }
        __syncthreads();

        const uint32_t sq = sb + S_Q;
        const uint32_t sk = sb + S_KB + (kt & 1) * 8192;

        float acc[8][4];
        #pragma unroll
        for (int j = 0; j < 8; j++)
            #pragma unroll
            for (int e = 0; e < 4; e++) acc[j][e] = 0.0f;

        #pragma unroll
        for (int ks = 0; ks < 4; ks++) {
            uint32_t a[4];
            ldsm_x4(a, sq + SW128((uint32_t)((wm + arow) * 128 + ks * 32 + abyt)));
            #pragma unroll
            for (int nb = 0; nb < 4; nb++) {
                uint32_t bh4[4];
                ldsm_x4(bh4, sk + SW128((uint32_t)((nb * 16 + arow) * 128 + ks * 32 + abyt)));
                mma_f16(acc[nb*2],   a, bh4[0], bh4[2]);
                mma_f16(acc[nb*2+1], a, bh4[1], bh4[3]);
            }
        }

        const int r0g = qBase + wm + row0;
        float tmx0 = -INFINITY, tmx1 = -INFINITY;
        #pragma unroll
        for (int nj = 0; nj < 8; nj++) {
            const int col = kt * 64 + nj * 8 + (lane & 3) * 2;
            const size_t o0 = (size_t)r0g * SEQ + col;
            const size_t o1 = o0 + (size_t)8 * SEQ;
            int2 ma = *(const int2*)&mp[o0];
            int2 mb = *(const int2*)&mp[o1];
            acc[nj][0] = ma.x ? acc[nj][0] * 0.125f : -1e9f;
            acc[nj][1] = ma.y ? acc[nj][1] * 0.125f : -1e9f;
            acc[nj][2] = mb.x ? acc[nj][2] * 0.125f : -1e9f;
            acc[nj][3] = mb.y ? acc[nj][3] * 0.125f : -1e9f;
            tmx0 = fmaxf(tmx0, fmaxf(acc[nj][0], acc[nj][1]));
            tmx1 = fmaxf(tmx1, fmaxf(acc[nj][2], acc[nj][3]));
        }
        tmx0 = fmaxf(tmx0, __shfl_xor_sync(0xffffffffu, tmx0, 1));
        tmx0 = fmaxf(tmx0, __shfl_xor_sync(0xffffffffu, tmx0, 2));
        tmx1 = fmaxf(tmx1, __shfl_xor_sync(0xffffffffu, tmx1, 1));
        tmx1 = fmaxf(tmx1, __shfl_xor_sync(0xffffffffu, tmx1, 2));

        const float m0n = fmaxf(m0, tmx0);
        const float m1n = fmaxf(m1, tmx1);
        float s0 = 0.0f, s1 = 0.0f;
        #pragma unroll
        for (int nj = 0; nj < 8; nj++) {
            s0 += __expf(acc[nj][0] - m0n) + __expf(acc[nj][1] - m0n);
            s1 += __expf(acc[nj][2] - m1n) + __expf(acc[nj][3] - m1n);
        }
        s0 += __shfl_xor_sync(0xffffffffu, s0, 1);
        s0 += __shfl_xor_sync(0xffffffffu, s0, 2);
        s1 += __shfl_xor_sync(0xffffffffu, s1, 1);
        s1 += __shfl_xor_sync(0xffffffffu, s1, 2);

        l0 = l0 * __expf(m0 - m0n) + s0;  m0 = m0n;
        l1 = l1 * __expf(m1 - m1n) + s1;  m1 = m1n;

        __syncthreads();
    }

    if ((lane & 3) == 0) {
        const int r0g = qBase + wm + row0;
        g_M[(size_t)bh * SEQ + r0g]     = m0;
        g_L[(size_t)bh * SEQ + r0g]     = l0;
        g_M[(size_t)bh * SEQ + r0g + 8] = m1;
        g_L[(size_t)bh * SEQ + r0g + 8] = l1;
    }
}

// ---------------------------------------------------------------------------
// Kernel B: recompute QK^T (2-term: Qh.Kh + Ql.Kh), normalize, write attn
// once, and accumulate out = P . V (2-term: Ph.Vh + Pl.Vh, P split in regs).
// CTA: 128 threads, 64 q x 64 d; 32 k-tiles of 64. SMEM ~41 KB.
// ---------------------------------------------------------------------------
#define B_QHI 0
#define B_QLO 8192
#define B_KB  16384    // stage buf at 16384 + buf*8192
#define B_V   32768
#define B_M   40960
#define B_IL  41216
#define B_SMEM 41472

__global__ __launch_bounds__(128, 3)
void recompute_pv(const int* __restrict__ mask, float* __restrict__ attn,
                  float* __restrict__ out)
{
    extern __shared__ char smem[];
    const uint32_t sb = smem_u32(smem);
    const int tid = threadIdx.x, wid = tid >> 5, lane = tid & 31;

    const int bh = blockIdx.y, b = bh >> 4;
    const int qBase = blockIdx.x * 64;

    float* sm_m  = (float*)(smem + B_M);
    float* sm_il = (float*)(smem + B_IL);
    if (tid < 64) {
        sm_m[tid]  = g_M[(size_t)bh * SEQ + qBase + tid];
        sm_il[tid] = 1.0f / g_L[(size_t)bh * SEQ + qBase + tid];
    }

    const char* qhg = (const char*)(g_Qh + (size_t)(bh * SEQ + qBase) * DKDIM);
    const char* qlg = (const char*)(g_Ql + (size_t)(bh * SEQ + qBase) * DKDIM);
    #pragma unroll
    for (int i = tid; i < 512; i += 128) {
        const int r = i >> 3, c = i & 7;
        const uint32_t sw = SW128((uint32_t)(r * 128 + c * 16));
        CP16(sb + B_QHI + sw, qhg + r * 128 + c * 16);
        CP16(sb + B_QLO + sw, qlg + r * 128 + c * 16);
    }
    CP_COMMIT;

    const char* khg = (const char*)(g_Kh + (size_t)bh * SEQ * DKDIM);
    const char* vhg = (const char*)(g_Vh + (size_t)bh * SEQ * DKDIM);

    auto issueK = [&](int kt, int buf) {
        #pragma unroll
        for (int i = tid; i < 512; i += 128) {
            const int r = i >> 3, c = i & 7;
            CP16(sb + B_KB + buf * 8192 + SW128((uint32_t)(r * 128 + c * 16)),
                 khg + (size_t)(kt * 64 + r) * 128 + c * 16);
        }
        CP_COMMIT;
    };
    auto issueV = [&](int kt) {
        #pragma unroll
        for (int i = tid; i < 512; i += 128) {
            const int r = i >> 3, c = i & 7;
            CP16(sb + B_V + SW128((uint32_t)(r * 128 + c * 16)),
                 vhg + (size_t)(kt * 64 + r) * 128 + c * 16);
        }
        CP_COMMIT;
    };
    issueK(0, 0);
    __syncthreads();   // sm_m/sm_il visible

    const int wm   = wid * 16;
    const int arow = lane & 15;
    const int abyt = (lane >> 4) << 4;
    const int row0 = lane >> 2;

    const float m0r  = sm_m[wm + row0],  m8r  = sm_m[wm + row0 + 8];
    const float il0r = sm_il[wm + row0], il8r = sm_il[wm + row0 + 8];

    const int* mp = mask + (size_t)b  * SEQ * SEQ;
    float*     ap = attn + (size_t)bh * SEQ * SEQ;

    float oacc[8][4];
    #pragma unroll
    for (int j = 0; j < 8; j++)
        #pragma unroll
        for (int e = 0; e < 4; e++) oacc[j][e] = 0.0f;

    for (int kt = 0; kt < 32; kt++) {
        // Issue V(kt) first, then K(kt+1): lets PV wait skip K(kt+1).
        issueV(kt);
        if (kt + 1 < 32) { issueK(kt + 1, (kt + 1) & 1); CP_WAIT2; }
        else             { CP_WAIT1; }
        __syncthreads();

        const uint32_t sqh = sb + B_QHI, sql = sb + B_QLO;
        const uint32_t skh = sb + B_KB + (kt & 1) * 8192;

        // ---- QK^T: 2-term fp16 ----
        float acc[8][4];
        #pragma unroll
        for (int j = 0; j < 8; j++)
            #pragma unroll
            for (int e = 0; e < 4; e++) acc[j][e] = 0.0f;

        #pragma unroll
        for (int ks = 0; ks < 4; ks++) {
            uint32_t ah[4], al[4];
            const uint32_t aoff = SW128((uint32_t)((wm + arow) * 128 + ks * 32 + abyt));
            ldsm_x4(ah, sqh + aoff);
            ldsm_x4(al, sql + aoff);
            #pragma unroll
            for (int nb = 0; nb < 4; nb++) {
                uint32_t bh4[4];
                ldsm_x4(bh4, skh + SW128((uint32_t)((nb * 16 + arow) * 128 + ks * 32 + abyt)));
                mma_f16(acc[nb*2],   ah, bh4[0], bh4[2]);
                mma_f16(acc[nb*2+1], ah, bh4[1], bh4[3]);
                mma_f16(acc[nb*2],   al, bh4[0], bh4[2]);
                mma_f16(acc[nb*2+1], al, bh4[1], bh4[3]);
            }
        }

        // ---- mask + normalize + write attn + build P A-fragments ----
        uint32_t pa_hi[4][4], pa_lo[4][4];
        const int r0g = qBase + wm + row0;
        #pragma unroll
        for (int nj = 0; nj < 8; nj++) {
            const int col = kt * 64 + nj * 8 + (lane & 3) * 2;
            const size_t o0 = (size_t)r0g * SEQ + col;
            const size_t o1 = o0 + (size_t)8 * SEQ;
            int2 ma = *(const int2*)&mp[o0];
            int2 mb = *(const int2*)&mp[o1];
            float2 p0, p1;
            p0.x = __expf((ma.x ? acc[nj][0] * 0.125f : -1e9f) - m0r) * il0r;
            p0.y = __expf((ma.y ? acc[nj][1] * 0.125f : -1e9f) - m0r) * il0r;
            p1.x = __expf((mb.x ? acc[nj][2] * 0.125f : -1e9f) - m8r) * il8r;
            p1.y = __expf((mb.y ? acc[nj][3] * 0.125f : -1e9f) - m8r) * il8r;
            *(float2*)&ap[o0] = p0;
            *(float2*)&ap[o1] = p1;
            const int ks = nj >> 1, half = nj & 1;
            splith2(p0.x, p0.y, pa_hi[ks][half*2],   pa_lo[ks][half*2]);
            splith2(p1.x, p1.y, pa_hi[ks][half*2+1], pa_lo[ks][half*2+1]);
        }

        // ---- P . V: 2-term fp16 (V(kt) ready; K(kt+1) may still be in flight)
        if (kt + 1 < 32) { CP_WAIT1; } else { CP_WAIT0; }
        __syncthreads();
        const uint32_t sv = sb + B_V;
        #pragma unroll
        for (int ks = 0; ks < 4; ks++) {
            #pragma unroll
            for (int ng = 0; ng < 4; ng++) {
                uint32_t bh4[4];
                ldsm_x4_t(bh4, sv + SW128((uint32_t)((ks * 16 + arow) * 128 + ng * 32 + abyt)));
                mma_f16(oacc[ng*2],   pa_hi[ks], bh4[0], bh4[1]);
                mma_f16(oacc[ng*2+1], pa_hi[ks], bh4[2], bh4[3]);
                mma_f16(oacc[ng*2],   pa_lo[ks], bh4[0], bh4[1]);
                mma_f16(oacc[ng*2+1], pa_lo[ks], bh4[2], bh4[3]);
            }
        }
        __syncthreads();   // protect V stage + K buf before next iteration
    }

    float* op = out + (size_t)bh * SEQ * DKDIM;
    const int r0 = qBase + wm + row0;
    #pragma unroll
    for (int j = 0; j < 8; j++) {
        const int col = j * 8 + (lane & 3) * 2;
        *(float2*)&op[(size_t)r0 * DKDIM + col]       = make_float2(oacc[j][0], oacc[j][1]);
        *(float2*)&op[(size_t)(r0 + 8) * DKDIM + col] = make_float2(oacc[j][2], oacc[j][3]);
    }
}

// ---------------------------------------------------------------------------
extern "C" void kernel_launch(void* const* d_in, const int* in_sizes, int n_in,
                              void* d_out, int out_size)
{
    const float* Q    = (const float*)d_in[0];
    const float* K    = (const float*)d_in[1];
    const float* V    = (const float*)d_in[2];
    const int*   mask = (const int*)  d_in[3];

    float* out  = (float*)d_out;
    float* attn = out + (size_t)BH * SEQ * DKDIM;

    cudaFuncSetAttribute(stats_pass,   cudaFuncAttributeMaxDynamicSharedMemorySize, S_SMEM);
    cudaFuncSetAttribute(recompute_pv, cudaFuncAttributeMaxDynamicSharedMemorySize, B_SMEM);

    preconv<<<2048, 256>>>(Q, K, V);
    stats_pass<<<dim3(SEQ / 64, BH), 128, S_SMEM>>>(mask);
    recompute_pv<<<dim3(SEQ / 64, BH), 128, B_SMEM>>>(mask, attn, out);
}

// round 11
// speedup vs baseline: 3.0566x; 1.0723x over previous
#include <cuda_runtime.h>
#include <cuda_fp16.h>
#include <cstdint>
#include <math.h>

#define BATCH 4
#define HEADS 16
#define SEQ   2048
#define DKDIM 64
#define BH    (BATCH*HEADS)
#define NELEM (BH*SEQ*DKDIM)   // 8,388,608

// Scratch (allowed: __device__ global arrays)
__device__ float g_M[BH * SEQ];
__device__ float g_L[BH * SEQ];
__device__ __half g_Qh[NELEM], g_Ql[NELEM];   // Q split hi/lo fp16
__device__ __half g_Kh[NELEM];                // K single fp16
__device__ __half g_Vh[NELEM];                // V single fp16
__device__ unsigned long long g_Mb[BATCH * SEQ * (SEQ / 64)];  // bit-packed mask, 2 MB

// ---------------------------------------------------------------------------
// PTX helpers
// ---------------------------------------------------------------------------
__device__ __forceinline__ uint32_t smem_u32(const void* p) {
    uint32_t a;
    asm("{ .reg .u64 t; cvta.to.shared.u64 t, %1; cvt.u32.u64 %0, t; }"
        : "=r"(a) : "l"(p));
    return a;
}
__device__ __forceinline__ void ldsm_x4(uint32_t (&r)[4], uint32_t addr) {
    asm volatile("ldmatrix.sync.aligned.m8n8.x4.shared.b16 {%0,%1,%2,%3}, [%4];"
        : "=r"(r[0]), "=r"(r[1]), "=r"(r[2]), "=r"(r[3]) : "r"(addr));
}
__device__ __forceinline__ void ldsm_x4_t(uint32_t (&r)[4], uint32_t addr) {
    asm volatile("ldmatrix.sync.aligned.m8n8.x4.trans.shared.b16 {%0,%1,%2,%3}, [%4];"
        : "=r"(r[0]), "=r"(r[1]), "=r"(r[2]), "=r"(r[3]) : "r"(addr));
}
__device__ __forceinline__ void mma_f16(float (&c)[4], const uint32_t (&a)[4],
                                        uint32_t b0, uint32_t b1) {
    asm volatile("mma.sync.aligned.m16n8k16.row.col.f32.f16.f16.f32 "
        "{%0,%1,%2,%3}, {%4,%5,%6,%7}, {%8,%9}, {%0,%1,%2,%3};"
        : "+f"(c[0]), "+f"(c[1]), "+f"(c[2]), "+f"(c[3])
        : "r"(a[0]), "r"(a[1]), "r"(a[2]), "r"(a[3]), "r"(b0), "r"(b1));
}
#define CP16(dst, src) \
    asm volatile("cp.async.cg.shared.global [%0], [%1], 16;" \
                 :: "r"(dst), "l"(src) : "memory")
#define CP_COMMIT  asm volatile("cp.async.commit_group;" ::: "memory")
#define CP_WAIT0   asm volatile("cp.async.wait_group 0;" ::: "memory")

#define SW128(b) ((b) ^ (((b) >> 3) & 0x70))

__device__ __forceinline__ uint32_t pack_h2(float x, float y) {
    __half2 h = __floats2half2_rn(x, y);
    return *reinterpret_cast<uint32_t*>(&h);
}
__device__ __forceinline__ void splith2(float x, float y, uint32_t& hi, uint32_t& lo) {
    __half2 h = __floats2half2_rn(x, y);
    hi = *reinterpret_cast<uint32_t*>(&h);
    lo = pack_h2(x - __low2float(h), y - __high2float(h));
}

// ---------------------------------------------------------------------------
// Kernel 0a: preconvert. Q -> fp16 hi/lo, K -> fp16, V -> fp16.
// ---------------------------------------------------------------------------
__global__ void preconv(const float* __restrict__ Q, const float* __restrict__ K,
                        const float* __restrict__ V)
{
    const int n2 = NELEM / 2;
    uint32_t* qh = (uint32_t*)g_Qh; uint32_t* ql = (uint32_t*)g_Ql;
    uint32_t* kh = (uint32_t*)g_Kh; uint32_t* vh = (uint32_t*)g_Vh;
    for (int i = blockIdx.x * blockDim.x + threadIdx.x; i < n2;
         i += gridDim.x * blockDim.x) {
        float2 q = ((const float2*)Q)[i];
        float2 k = ((const float2*)K)[i];
        float2 v = ((const float2*)V)[i];
        splith2(q.x, q.y, qh[i], ql[i]);
        kh[i] = pack_h2(k.x, k.y);
        vh[i] = pack_h2(v.x, v.y);
    }
}

// ---------------------------------------------------------------------------
// Kernel 0b: pack mask int32 -> bits. One warp per 64-int chunk (ballot).
// ---------------------------------------------------------------------------
__global__ void pack_mask(const int* __restrict__ mask)
{
    const int lane  = threadIdx.x & 31;
    const int warp  = (blockIdx.x * blockDim.x + threadIdx.x) >> 5;
    const int nwarp = (gridDim.x * blockDim.x) >> 5;
    const int nchunk = BATCH * SEQ * (SEQ / 64);
    for (int c = warp; c < nchunk; c += nwarp) {
        const int* p = mask + (size_t)c * 64;
        unsigned lo = __ballot_sync(0xffffffffu, p[lane] != 0);
        unsigned hi = __ballot_sync(0xffffffffu, p[32 + lane] != 0);
        if (lane == 0)
            g_Mb[c] = ((unsigned long long)hi << 32) | lo;
    }
}

// ---------------------------------------------------------------------------
// Kernel A: softmax stats only. 1-term fp16 QK^T (Qh . Kh).
// CTA: 128 threads (4 warps), 64 q x 2048 k in 32 tiles of 64.
// K double-buffered; ONE wait + ONE sync per tile; bitmask prefetched.
// ---------------------------------------------------------------------------
#define S_Q  0
#define S_KB 8192    // stage buf at 8192 + buf*8192
#define S_SMEM 24576

__global__ __launch_bounds__(128)
void stats_pass()
{
    extern __shared__ char smem[];
    const uint32_t sb = smem_u32(smem);
    const int tid = threadIdx.x, wid = tid >> 5, lane = tid & 31;

    const int bh = blockIdx.y, b = bh >> 4;
    const int qBase = blockIdx.x * 64;

    const char* qhg = (const char*)(g_Qh + (size_t)(bh * SEQ + qBase) * DKDIM);
    #pragma unroll
    for (int i = tid; i < 512; i += 128) {
        const int r = i >> 3, c = i & 7;
        CP16(sb + S_Q + SW128((uint32_t)(r * 128 + c * 16)), qhg + r * 128 + c * 16);
    }

    const char* khg = (const char*)(g_Kh + (size_t)bh * SEQ * DKDIM);
    auto issueK = [&](int kt, int buf) {
        #pragma unroll
        for (int i = tid; i < 512; i += 128) {
            const int r = i >> 3, c = i & 7;
            CP16(sb + S_KB + buf * 8192 + SW128((uint32_t)(r * 128 + c * 16)),
                 khg + (size_t)(kt * 64 + r) * 128 + c * 16);
        }
        CP_COMMIT;
    };
    issueK(0, 0);   // commits Q + K(0) as one group

    const int wm   = wid * 16;
    const int arow = lane & 15;
    const int abyt = (lane >> 4) << 4;
    const int row0 = lane >> 2;
    const int r0g  = qBase + wm + row0;

    const unsigned long long* bmp = g_Mb + (size_t)b * SEQ * 32;
    float m0 = -INFINITY, m1 = -INFINITY, l0 = 0.0f, l1 = 0.0f;

    for (int kt = 0; kt < 32; kt++) {
        CP_WAIT0;
        __syncthreads();
        if (kt + 1 < 32) issueK(kt + 1, (kt + 1) & 1);

        // Mask bits for this tile (L2-resident), issued before the MMAs.
        const unsigned long long mb0 = bmp[(size_t)r0g * 32 + kt];
        const unsigned long long mb1 = bmp[(size_t)(r0g + 8) * 32 + kt];

        const uint32_t sq = sb + S_Q;
        const uint32_t sk = sb + S_KB + (kt & 1) * 8192;

        float acc[8][4];
        #pragma unroll
        for (int j = 0; j < 8; j++)
            #pragma unroll
            for (int e = 0; e < 4; e++) acc[j][e] = 0.0f;

        #pragma unroll
        for (int ks = 0; ks < 4; ks++) {
            uint32_t a[4];
            ldsm_x4(a, sq + SW128((uint32_t)((wm + arow) * 128 + ks * 32 + abyt)));
            #pragma unroll
            for (int nb = 0; nb < 4; nb++) {
                uint32_t bh4[4];
                ldsm_x4(bh4, sk + SW128((uint32_t)((nb * 16 + arow) * 128 + ks * 32 + abyt)));
                mma_f16(acc[nb*2],   a, bh4[0], bh4[2]);
                mma_f16(acc[nb*2+1], a, bh4[1], bh4[3]);
            }
        }

        float tmx0 = -INFINITY, tmx1 = -INFINITY;
        #pragma unroll
        for (int nj = 0; nj < 8; nj++) {
            const int c0 = nj * 8 + (lane & 3) * 2;
            acc[nj][0] = ((mb0 >> c0) & 1)       ? acc[nj][0] * 0.125f : -1e9f;
            acc[nj][1] = ((mb0 >> (c0 + 1)) & 1) ? acc[nj][1] * 0.125f : -1e9f;
            acc[nj][2] = ((mb1 >> c0) & 1)       ? acc[nj][2] * 0.125f : -1e9f;
            acc[nj][3] = ((mb1 >> (c0 + 1)) & 1) ? acc[nj][3] * 0.125f : -1e9f;
            tmx0 = fmaxf(tmx0, fmaxf(acc[nj][0], acc[nj][1]));
            tmx1 = fmaxf(tmx1, fmaxf(acc[nj][2], acc[nj][3]));
        }
        tmx0 = fmaxf(tmx0, __shfl_xor_sync(0xffffffffu, tmx0, 1));
        tmx0 = fmaxf(tmx0, __shfl_xor_sync(0xffffffffu, tmx0, 2));
        tmx1 = fmaxf(tmx1, __shfl_xor_sync(0xffffffffu, tmx1, 1));
        tmx1 = fmaxf(tmx1, __shfl_xor_sync(0xffffffffu, tmx1, 2));

        const float m0n = fmaxf(m0, tmx0);
        const float m1n = fmaxf(m1, tmx1);
        float s0 = 0.0f, s1 = 0.0f;
        #pragma unroll
        for (int nj = 0; nj < 8; nj++) {
            s0 += __expf(acc[nj][0] - m0n) + __expf(acc[nj][1] - m0n);
            s1 += __expf(acc[nj][2] - m1n) + __expf(acc[nj][3] - m1n);
        }
        s0 += __shfl_xor_sync(0xffffffffu, s0, 1);
        s0 += __shfl_xor_sync(0xffffffffu, s0, 2);
        s1 += __shfl_xor_sync(0xffffffffu, s1, 1);
        s1 += __shfl_xor_sync(0xffffffffu, s1, 2);

        l0 = l0 * __expf(m0 - m0n) + s0;  m0 = m0n;
        l1 = l1 * __expf(m1 - m1n) + s1;  m1 = m1n;
    }

    if ((lane & 3) == 0) {
        g_M[(size_t)bh * SEQ + r0g]     = m0;
        g_L[(size_t)bh * SEQ + r0g]     = l0;
        g_M[(size_t)bh * SEQ + r0g + 8] = m1;
        g_L[(size_t)bh * SEQ + r0g + 8] = l1;
    }
}

// ---------------------------------------------------------------------------
// Kernel B: recompute QK^T (Qh.Kh + Ql.Kh), normalize, write attn once,
// out += P.V (Ph.Vh + Pl.Vh). K and V both double-buffered, ONE cp.async
// group + ONE wait + ONE sync per tile. Bitmask prefetched. SMEM ~49 KB.
// ---------------------------------------------------------------------------
#define B_QHI 0
#define B_QLO 8192
#define B_KB  16384    // K stage buf at 16384 + buf*8192
#define B_VB  32768    // V stage buf at 32768 + buf*8192
#define B_M   49152
#define B_IL  49408
#define B_SMEM 49664

__global__ __launch_bounds__(128, 3)
void recompute_pv(float* __restrict__ attn, float* __restrict__ out)
{
    extern __shared__ char smem[];
    const uint32_t sb = smem_u32(smem);
    const int tid = threadIdx.x, wid = tid >> 5, lane = tid & 31;

    const int bh = blockIdx.y, b = bh >> 4;
    const int qBase = blockIdx.x * 64;

    float* sm_m  = (float*)(smem + B_M);
    float* sm_il = (float*)(smem + B_IL);
    if (tid < 64) {
        sm_m[tid]  = g_M[(size_t)bh * SEQ + qBase + tid];
        sm_il[tid] = 1.0f / g_L[(size_t)bh * SEQ + qBase + tid];
    }

    const char* qhg = (const char*)(g_Qh + (size_t)(bh * SEQ + qBase) * DKDIM);
    const char* qlg = (const char*)(g_Ql + (size_t)(bh * SEQ + qBase) * DKDIM);
    #pragma unroll
    for (int i = tid; i < 512; i += 128) {
        const int r = i >> 3, c = i & 7;
        const uint32_t sw = SW128((uint32_t)(r * 128 + c * 16));
        CP16(sb + B_QHI + sw, qhg + r * 128 + c * 16);
        CP16(sb + B_QLO + sw, qlg + r * 128 + c * 16);
    }

    const char* khg = (const char*)(g_Kh + (size_t)bh * SEQ * DKDIM);
    const char* vhg = (const char*)(g_Vh + (size_t)bh * SEQ * DKDIM);

    // K + V for tile kt as ONE commit group.
    auto issueKV = [&](int kt, int buf) {
        #pragma unroll
        for (int i = tid; i < 512; i += 128) {
            const int r = i >> 3, c = i & 7;
            const uint32_t sw = SW128((uint32_t)(r * 128 + c * 16));
            CP16(sb + B_KB + buf * 8192 + sw, khg + (size_t)(kt * 64 + r) * 128 + c * 16);
            CP16(sb + B_VB + buf * 8192 + sw, vhg + (size_t)(kt * 64 + r) * 128 + c * 16);
        }
        CP_COMMIT;
    };
    issueKV(0, 0);   // commits Q + K(0) + V(0) as one group
    __syncthreads(); // sm_m/sm_il visible

    const int wm   = wid * 16;
    const int arow = lane & 15;
    const int abyt = (lane >> 4) << 4;
    const int row0 = lane >> 2;
    const int r0g  = qBase + wm + row0;

    const float m0r  = sm_m[wm + row0],  m8r  = sm_m[wm + row0 + 8];
    const float il0r = sm_il[wm + row0], il8r = sm_il[wm + row0 + 8];

    const unsigned long long* bmp = g_Mb + (size_t)b * SEQ * 32;
    float* ap = attn + (size_t)bh * SEQ * SEQ;

    float oacc[8][4];
    #pragma unroll
    for (int j = 0; j < 8; j++)
        #pragma unroll
        for (int e = 0; e < 4; e++) oacc[j][e] = 0.0f;

    for (int kt = 0; kt < 32; kt++) {
        CP_WAIT0;
        __syncthreads();
        if (kt + 1 < 32) issueKV(kt + 1, (kt + 1) & 1);

        const unsigned long long mb0 = bmp[(size_t)r0g * 32 + kt];
        const unsigned long long mb1 = bmp[(size_t)(r0g + 8) * 32 + kt];

        const int buf = kt & 1;
        const uint32_t sqh = sb + B_QHI, sql = sb + B_QLO;
        const uint32_t skh = sb + B_KB + buf * 8192;
        const uint32_t sv  = sb + B_VB + buf * 8192;

        // ---- QK^T: 2-term fp16 ----
        float acc[8][4];
        #pragma unroll
        for (int j = 0; j < 8; j++)
            #pragma unroll
            for (int e = 0; e < 4; e++) acc[j][e] = 0.0f;

        #pragma unroll
        for (int ks = 0; ks < 4; ks++) {
            uint32_t ah[4], al[4];
            const uint32_t aoff = SW128((uint32_t)((wm + arow) * 128 + ks * 32 + abyt));
            ldsm_x4(ah, sqh + aoff);
            ldsm_x4(al, sql + aoff);
            #pragma unroll
            for (int nb = 0; nb < 4; nb++) {
                uint32_t bh4[4];
                ldsm_x4(bh4, skh + SW128((uint32_t)((nb * 16 + arow) * 128 + ks * 32 + abyt)));
                mma_f16(acc[nb*2],   ah, bh4[0], bh4[2]);
                mma_f16(acc[nb*2+1], ah, bh4[1], bh4[3]);
                mma_f16(acc[nb*2],   al, bh4[0], bh4[2]);
                mma_f16(acc[nb*2+1], al, bh4[1], bh4[3]);
            }
        }

        // ---- mask + normalize + write attn + build P A-fragments ----
        uint32_t pa_hi[4][4], pa_lo[4][4];
        #pragma unroll
        for (int nj = 0; nj < 8; nj++) {
            const int c0  = nj * 8 + (lane & 3) * 2;
            const int col = kt * 64 + c0;
            const size_t o0 = (size_t)r0g * SEQ + col;
            const size_t o1 = o0 + (size_t)8 * SEQ;
            float2 p0, p1;
            p0.x = __expf((((mb0 >> c0) & 1)       ? acc[nj][0] * 0.125f : -1e9f) - m0r) * il0r;
            p0.y = __expf((((mb0 >> (c0 + 1)) & 1) ? acc[nj][1] * 0.125f : -1e9f) - m0r) * il0r;
            p1.x = __expf((((mb1 >> c0) & 1)       ? acc[nj][2] * 0.125f : -1e9f) - m8r) * il8r;
            p1.y = __expf((((mb1 >> (c0 + 1)) & 1) ? acc[nj][3] * 0.125f : -1e9f) - m8r) * il8r;
            *(float2*)&ap[o0] = p0;
            *(float2*)&ap[o1] = p1;
            const int ks = nj >> 1, half = nj & 1;
            splith2(p0.x, p0.y, pa_hi[ks][half*2],   pa_lo[ks][half*2]);
            splith2(p1.x, p1.y, pa_hi[ks][half*2+1], pa_lo[ks][half*2+1]);
        }

        // ---- P . V: 2-term fp16 (V(kt) already resident) ----
        #pragma unroll
        for (int ks = 0; ks < 4; ks++) {
            #pragma unroll
            for (int ng = 0; ng < 4; ng++) {
                uint32_t bh4[4];
                ldsm_x4_t(bh4, sv + SW128((uint32_t)((ks * 16 + arow) * 128 + ng * 32 + abyt)));
                mma_f16(oacc[ng*2],   pa_hi[ks], bh4[0], bh4[1]);
                mma_f16(oacc[ng*2+1], pa_hi[ks], bh4[2], bh4[3]);
                mma_f16(oacc[ng*2],   pa_lo[ks], bh4[0], bh4[1]);
                mma_f16(oacc[ng*2+1], pa_lo[ks], bh4[2], bh4[3]);
            }
        }
    }

    float* op = out + (size_t)bh * SEQ * DKDIM;
    #pragma unroll
    for (int j = 0; j < 8; j++) {
        const int col = j * 8 + (lane & 3) * 2;
        *(float2*)&op[(size_t)r0g * DKDIM + col]       = make_float2(oacc[j][0], oacc[j][1]);
        *(float2*)&op[(size_t)(r0g + 8) * DKDIM + col] = make_float2(oacc[j][2], oacc[j][3]);
    }
}

// ---------------------------------------------------------------------------
extern "C" void kernel_launch(void* const* d_in, const int* in_sizes, int n_in,
                              void* d_out, int out_size)
{
    const float* Q    = (const float*)d_in[0];
    const float* K    = (const float*)d_in[1];
    const float* V    = (const float*)d_in[2];
    const int*   mask = (const int*)  d_in[3];

    float* out  = (float*)d_out;
    float* attn = out + (size_t)BH * SEQ * DKDIM;

    cudaFuncSetAttribute(stats_pass,   cudaFuncAttributeMaxDynamicSharedMemorySize, S_SMEM);
    cudaFuncSetAttribute(recompute_pv, cudaFuncAttributeMaxDynamicSharedMemorySize, B_SMEM);

    preconv<<<2048, 256>>>(Q, K, V);
    pack_mask<<<1024, 256>>>(mask);
    stats_pass<<<dim3(SEQ / 64, BH), 128, S_SMEM>>>();
    recompute_pv<<<dim3(SEQ / 64, BH), 128, B_SMEM>>>(attn, out);
}

// round 12
// speedup vs baseline: 3.2370x; 1.0590x over previous
#include <cuda_runtime.h>
#include <cuda_fp16.h>
#include <cstdint>
#include <math.h>

#define BATCH 4
#define HEADS 16
#define SEQ   2048
#define DKDIM 64
#define BH    (BATCH*HEADS)
#define NELEM (BH*SEQ*DKDIM)   // 8,388,608

// Scratch (allowed: __device__ global arrays)
__device__ float g_M[BH * SEQ];
__device__ float g_L[BH * SEQ];
__device__ __half g_Qh[NELEM], g_Ql[NELEM];   // Q split hi/lo fp16
__device__ __half g_Kh[NELEM];                // K single fp16
__device__ __half g_Vh[NELEM];                // V single fp16
__device__ unsigned long long g_Mb[BATCH * SEQ * (SEQ / 64)];  // bit-packed mask, 2 MB

// ---------------------------------------------------------------------------
// PTX helpers
// ---------------------------------------------------------------------------
__device__ __forceinline__ uint32_t smem_u32(const void* p) {
    uint32_t a;
    asm("{ .reg .u64 t; cvta.to.shared.u64 t, %1; cvt.u32.u64 %0, t; }"
        : "=r"(a) : "l"(p));
    return a;
}
__device__ __forceinline__ void ldsm_x4(uint32_t (&r)[4], uint32_t addr) {
    asm volatile("ldmatrix.sync.aligned.m8n8.x4.shared.b16 {%0,%1,%2,%3}, [%4];"
        : "=r"(r[0]), "=r"(r[1]), "=r"(r[2]), "=r"(r[3]) : "r"(addr));
}
__device__ __forceinline__ void ldsm_x4_t(uint32_t (&r)[4], uint32_t addr) {
    asm volatile("ldmatrix.sync.aligned.m8n8.x4.trans.shared.b16 {%0,%1,%2,%3}, [%4];"
        : "=r"(r[0]), "=r"(r[1]), "=r"(r[2]), "=r"(r[3]) : "r"(addr));
}
__device__ __forceinline__ void mma_f16(float (&c)[4], const uint32_t (&a)[4],
                                        uint32_t b0, uint32_t b1) {
    asm volatile("mma.sync.aligned.m16n8k16.row.col.f32.f16.f16.f32 "
        "{%0,%1,%2,%3}, {%4,%5,%6,%7}, {%8,%9}, {%0,%1,%2,%3};"
        : "+f"(c[0]), "+f"(c[1]), "+f"(c[2]), "+f"(c[3])
        : "r"(a[0]), "r"(a[1]), "r"(a[2]), "r"(a[3]), "r"(b0), "r"(b1));
}
#define CP16(dst, src) \
    asm volatile("cp.async.cg.shared.global [%0], [%1], 16;" \
                 :: "r"(dst), "l"(src) : "memory")
#define CP_COMMIT  asm volatile("cp.async.commit_group;" ::: "memory")
#define CP_WAIT0   asm volatile("cp.async.wait_group 0;" ::: "memory")

#define SW128(b) ((b) ^ (((b) >> 3) & 0x70))

__device__ __forceinline__ uint32_t pack_h2(float x, float y) {
    __half2 h = __floats2half2_rn(x, y);
    return *reinterpret_cast<uint32_t*>(&h);
}
__device__ __forceinline__ void splith2(float x, float y, uint32_t& hi, uint32_t& lo) {
    __half2 h = __floats2half2_rn(x, y);
    hi = *reinterpret_cast<uint32_t*>(&h);
    lo = pack_h2(x - __low2float(h), y - __high2float(h));
}

// ---------------------------------------------------------------------------
// Kernel 0a: preconvert. Q -> fp16 hi/lo, K -> fp16, V -> fp16.
// ---------------------------------------------------------------------------
__global__ void preconv(const float* __restrict__ Q, const float* __restrict__ K,
                        const float* __restrict__ V)
{
    const int n2 = NELEM / 2;
    uint32_t* qh = (uint32_t*)g_Qh; uint32_t* ql = (uint32_t*)g_Ql;
    uint32_t* kh = (uint32_t*)g_Kh; uint32_t* vh = (uint32_t*)g_Vh;
    for (int i = blockIdx.x * blockDim.x + threadIdx.x; i < n2;
         i += gridDim.x * blockDim.x) {
        float2 q = ((const float2*)Q)[i];
        float2 k = ((const float2*)K)[i];
        float2 v = ((const float2*)V)[i];
        splith2(q.x, q.y, qh[i], ql[i]);
        kh[i] = pack_h2(k.x, k.y);
        vh[i] = pack_h2(v.x, v.y);
    }
}

// ---------------------------------------------------------------------------
// Kernel 0b: pack mask int32 -> bits. One warp per 64-int chunk (ballot).
// ---------------------------------------------------------------------------
__global__ void pack_mask(const int* __restrict__ mask)
{
    const int lane  = threadIdx.x & 31;
    const int warp  = (blockIdx.x * blockDim.x + threadIdx.x) >> 5;
    const int nwarp = (gridDim.x * blockDim.x) >> 5;
    const int nchunk = BATCH * SEQ * (SEQ / 64);
    for (int c = warp; c < nchunk; c += nwarp) {
        const int* p = mask + (size_t)c * 64;
        unsigned lo = __ballot_sync(0xffffffffu, p[lane] != 0);
        unsigned hi = __ballot_sync(0xffffffffu, p[32 + lane] != 0);
        if (lane == 0)
            g_Mb[c] = ((unsigned long long)hi << 32) | lo;
    }
}

// ---------------------------------------------------------------------------
// Kernel A: softmax stats only. 1-term fp16 QK^T (Qh . Kh).
// CTA: 128 threads (4 warps), 64 q x 2048 k in 32 tiles of 64.
// K double-buffered; ONE wait + ONE sync per tile; bitmask prefetched.
// ---------------------------------------------------------------------------
#define S_Q  0
#define S_KB 8192    // stage buf at 8192 + buf*8192
#define S_SMEM 24576

__global__ __launch_bounds__(128)
void stats_pass()
{
    extern __shared__ char smem[];
    const uint32_t sb = smem_u32(smem);
    const int tid = threadIdx.x, wid = tid >> 5, lane = tid & 31;

    const int bh = blockIdx.y, b = bh >> 4;
    const int qBase = blockIdx.x * 64;

    const char* qhg = (const char*)(g_Qh + (size_t)(bh * SEQ + qBase) * DKDIM);
    #pragma unroll
    for (int i = tid; i < 512; i += 128) {
        const int r = i >> 3, c = i & 7;
        CP16(sb + S_Q + SW128((uint32_t)(r * 128 + c * 16)), qhg + r * 128 + c * 16);
    }

    const char* khg = (const char*)(g_Kh + (size_t)bh * SEQ * DKDIM);
    auto issueK = [&](int kt, int buf) {
        #pragma unroll
        for (int i = tid; i < 512; i += 128) {
            const int r = i >> 3, c = i & 7;
            CP16(sb + S_KB + buf * 8192 + SW128((uint32_t)(r * 128 + c * 16)),
                 khg + (size_t)(kt * 64 + r) * 128 + c * 16);
        }
        CP_COMMIT;
    };
    issueK(0, 0);   // commits Q + K(0) as one group

    const int wm   = wid * 16;
    const int arow = lane & 15;
    const int abyt = (lane >> 4) << 4;
    const int row0 = lane >> 2;
    const int r0g  = qBase + wm + row0;

    const unsigned long long* bmp = g_Mb + (size_t)b * SEQ * 32;
    float m0 = -INFINITY, m1 = -INFINITY, l0 = 0.0f, l1 = 0.0f;

    for (int kt = 0; kt < 32; kt++) {
        CP_WAIT0;
        __syncthreads();
        if (kt + 1 < 32) issueK(kt + 1, (kt + 1) & 1);

        const unsigned long long mb0 = bmp[(size_t)r0g * 32 + kt];
        const unsigned long long mb1 = bmp[(size_t)(r0g + 8) * 32 + kt];

        const uint32_t sq = sb + S_Q;
        const uint32_t sk = sb + S_KB + (kt & 1) * 8192;

        float acc[8][4];
        #pragma unroll
        for (int j = 0; j < 8; j++)
            #pragma unroll
            for (int e = 0; e < 4; e++) acc[j][e] = 0.0f;

        #pragma unroll
        for (int ks = 0; ks < 4; ks++) {
            uint32_t a[4];
            ldsm_x4(a, sq + SW128((uint32_t)((wm + arow) * 128 + ks * 32 + abyt)));
            #pragma unroll
            for (int nb = 0; nb < 4; nb++) {
                uint32_t bh4[4];
                ldsm_x4(bh4, sk + SW128((uint32_t)((nb * 16 + arow) * 128 + ks * 32 + abyt)));
                mma_f16(acc[nb*2],   a, bh4[0], bh4[2]);
                mma_f16(acc[nb*2+1], a, bh4[1], bh4[3]);
            }
        }

        float tmx0 = -INFINITY, tmx1 = -INFINITY;
        #pragma unroll
        for (int nj = 0; nj < 8; nj++) {
            const int c0 = nj * 8 + (lane & 3) * 2;
            acc[nj][0] = ((mb0 >> c0) & 1)       ? acc[nj][0] * 0.125f : -1e9f;
            acc[nj][1] = ((mb0 >> (c0 + 1)) & 1) ? acc[nj][1] * 0.125f : -1e9f;
            acc[nj][2] = ((mb1 >> c0) & 1)       ? acc[nj][2] * 0.125f : -1e9f;
            acc[nj][3] = ((mb1 >> (c0 + 1)) & 1) ? acc[nj][3] * 0.125f : -1e9f;
            tmx0 = fmaxf(tmx0, fmaxf(acc[nj][0], acc[nj][1]));
            tmx1 = fmaxf(tmx1, fmaxf(acc[nj][2], acc[nj][3]));
        }
        tmx0 = fmaxf(tmx0, __shfl_xor_sync(0xffffffffu, tmx0, 1));
        tmx0 = fmaxf(tmx0, __shfl_xor_sync(0xffffffffu, tmx0, 2));
        tmx1 = fmaxf(tmx1, __shfl_xor_sync(0xffffffffu, tmx1, 1));
        tmx1 = fmaxf(tmx1, __shfl_xor_sync(0xffffffffu, tmx1, 2));

        const float m0n = fmaxf(m0, tmx0);
        const float m1n = fmaxf(m1, tmx1);
        float s0 = 0.0f, s1 = 0.0f;
        #pragma unroll
        for (int nj = 0; nj < 8; nj++) {
            s0 += __expf(acc[nj][0] - m0n) + __expf(acc[nj][1] - m0n);
            s1 += __expf(acc[nj][2] - m1n) + __expf(acc[nj][3] - m1n);
        }
        s0 += __shfl_xor_sync(0xffffffffu, s0, 1);
        s0 += __shfl_xor_sync(0xffffffffu, s0, 2);
        s1 += __shfl_xor_sync(0xffffffffu, s1, 1);
        s1 += __shfl_xor_sync(0xffffffffu, s1, 2);

        l0 = l0 * __expf(m0 - m0n) + s0;  m0 = m0n;
        l1 = l1 * __expf(m1 - m1n) + s1;  m1 = m1n;
    }

    if ((lane & 3) == 0) {
        g_M[(size_t)bh * SEQ + r0g]     = m0;
        g_L[(size_t)bh * SEQ + r0g]     = l0;
        g_M[(size_t)bh * SEQ + r0g + 8] = m1;
        g_L[(size_t)bh * SEQ + r0g + 8] = l1;
    }
}

// ---------------------------------------------------------------------------
// Kernel B: recompute QK^T (Qh.Kh + Ql.Kh), normalize, write attn once,
// out += P.V (Ph.Vh + Pl.Vh). Per-ks fused epilogue+PV (8 fragment regs
// instead of 32) + __launch_bounds__(128,4) -> 4 CTAs/SM.
// ---------------------------------------------------------------------------
#define B_QHI 0
#define B_QLO 8192
#define B_KB  16384    // K stage buf at 16384 + buf*8192
#define B_VB  32768    // V stage buf at 32768 + buf*8192
#define B_M   49152
#define B_IL  49408
#define B_SMEM 49664

__global__ __launch_bounds__(128, 4)
void recompute_pv(float* __restrict__ attn, float* __restrict__ out)
{
    extern __shared__ char smem[];
    const uint32_t sb = smem_u32(smem);
    const int tid = threadIdx.x, wid = tid >> 5, lane = tid & 31;

    const int bh = blockIdx.y, b = bh >> 4;
    const int qBase = blockIdx.x * 64;

    float* sm_m  = (float*)(smem + B_M);
    float* sm_il = (float*)(smem + B_IL);
    if (tid < 64) {
        sm_m[tid]  = g_M[(size_t)bh * SEQ + qBase + tid];
        sm_il[tid] = 1.0f / g_L[(size_t)bh * SEQ + qBase + tid];
    }

    const char* qhg = (const char*)(g_Qh + (size_t)(bh * SEQ + qBase) * DKDIM);
    const char* qlg = (const char*)(g_Ql + (size_t)(bh * SEQ + qBase) * DKDIM);
    #pragma unroll
    for (int i = tid; i < 512; i += 128) {
        const int r = i >> 3, c = i & 7;
        const uint32_t sw = SW128((uint32_t)(r * 128 + c * 16));
        CP16(sb + B_QHI + sw, qhg + r * 128 + c * 16);
        CP16(sb + B_QLO + sw, qlg + r * 128 + c * 16);
    }

    const char* khg = (const char*)(g_Kh + (size_t)bh * SEQ * DKDIM);
    const char* vhg = (const char*)(g_Vh + (size_t)bh * SEQ * DKDIM);

    auto issueKV = [&](int kt, int buf) {
        #pragma unroll
        for (int i = tid; i < 512; i += 128) {
            const int r = i >> 3, c = i & 7;
            const uint32_t sw = SW128((uint32_t)(r * 128 + c * 16));
            CP16(sb + B_KB + buf * 8192 + sw, khg + (size_t)(kt * 64 + r) * 128 + c * 16);
            CP16(sb + B_VB + buf * 8192 + sw, vhg + (size_t)(kt * 64 + r) * 128 + c * 16);
        }
        CP_COMMIT;
    };
    issueKV(0, 0);
    __syncthreads();

    const int wm   = wid * 16;
    const int arow = lane & 15;
    const int abyt = (lane >> 4) << 4;
    const int row0 = lane >> 2;
    const int r0g  = qBase + wm + row0;

    const float m0r  = sm_m[wm + row0],  m8r  = sm_m[wm + row0 + 8];
    const float il0r = sm_il[wm + row0], il8r = sm_il[wm + row0 + 8];

    const unsigned long long* bmp = g_Mb + (size_t)b * SEQ * 32;
    float* ap = attn + (size_t)bh * SEQ * SEQ;

    float oacc[8][4];
    #pragma unroll
    for (int j = 0; j < 8; j++)
        #pragma unroll
        for (int e = 0; e < 4; e++) oacc[j][e] = 0.0f;

    for (int kt = 0; kt < 32; kt++) {
        CP_WAIT0;
        __syncthreads();
        if (kt + 1 < 32) issueKV(kt + 1, (kt + 1) & 1);

        const unsigned long long mb0 = bmp[(size_t)r0g * 32 + kt];
        const unsigned long long mb1 = bmp[(size_t)(r0g + 8) * 32 + kt];

        const int buf = kt & 1;
        const uint32_t sqh = sb + B_QHI, sql = sb + B_QLO;
        const uint32_t skh = sb + B_KB + buf * 8192;
        const uint32_t sv  = sb + B_VB + buf * 8192;

        // ---- QK^T: 2-term fp16 ----
        float acc[8][4];
        #pragma unroll
        for (int j = 0; j < 8; j++)
            #pragma unroll
            for (int e = 0; e < 4; e++) acc[j][e] = 0.0f;

        #pragma unroll
        for (int ks = 0; ks < 4; ks++) {
            uint32_t ah[4], al[4];
            const uint32_t aoff = SW128((uint32_t)((wm + arow) * 128 + ks * 32 + abyt));
            ldsm_x4(ah, sqh + aoff);
            ldsm_x4(al, sql + aoff);
            #pragma unroll
            for (int nb = 0; nb < 4; nb++) {
                uint32_t bh4[4];
                ldsm_x4(bh4, skh + SW128((uint32_t)((nb * 16 + arow) * 128 + ks * 32 + abyt)));
                mma_f16(acc[nb*2],   ah, bh4[0], bh4[2]);
                mma_f16(acc[nb*2+1], ah, bh4[1], bh4[3]);
                mma_f16(acc[nb*2],   al, bh4[0], bh4[2]);
                mma_f16(acc[nb*2+1], al, bh4[1], bh4[3]);
            }
        }

        // ---- per-ks: normalize + write attn + build fragments + PV MMAs ----
        #pragma unroll
        for (int ks = 0; ks < 4; ks++) {
            uint32_t ph[4], pl[4];
            #pragma unroll
            for (int half = 0; half < 2; half++) {
                const int nj  = ks * 2 + half;
                const int c0  = nj * 8 + (lane & 3) * 2;
                const int col = kt * 64 + c0;
                const size_t o0 = (size_t)r0g * SEQ + col;
                const size_t o1 = o0 + (size_t)8 * SEQ;
                float2 p0, p1;
                p0.x = __expf((((mb0 >> c0) & 1)       ? acc[nj][0] * 0.125f : -1e9f) - m0r) * il0r;
                p0.y = __expf((((mb0 >> (c0 + 1)) & 1) ? acc[nj][1] * 0.125f : -1e9f) - m0r) * il0r;
                p1.x = __expf((((mb1 >> c0) & 1)       ? acc[nj][2] * 0.125f : -1e9f) - m8r) * il8r;
                p1.y = __expf((((mb1 >> (c0 + 1)) & 1) ? acc[nj][3] * 0.125f : -1e9f) - m8r) * il8r;
                *(float2*)&ap[o0] = p0;
                *(float2*)&ap[o1] = p1;
                splith2(p0.x, p0.y, ph[half*2],   pl[half*2]);
                splith2(p1.x, p1.y, ph[half*2+1], pl[half*2+1]);
            }
            #pragma unroll
            for (int ng = 0; ng < 4; ng++) {
                uint32_t bh4[4];
                ldsm_x4_t(bh4, sv + SW128((uint32_t)((ks * 16 + arow) * 128 + ng * 32 + abyt)));
                mma_f16(oacc[ng*2],   ph, bh4[0], bh4[1]);
                mma_f16(oacc[ng*2+1], ph, bh4[2], bh4[3]);
                mma_f16(oacc[ng*2],   pl, bh4[0], bh4[1]);
                mma_f16(oacc[ng*2+1], pl, bh4[2], bh4[3]);
            }
        }
    }

    float* op = out + (size_t)bh * SEQ * DKDIM;
    #pragma unroll
    for (int j = 0; j < 8; j++) {
        const int col = j * 8 + (lane & 3) * 2;
        *(float2*)&op[(size_t)r0g * DKDIM + col]       = make_float2(oacc[j][0], oacc[j][1]);
        *(float2*)&op[(size_t)(r0g + 8) * DKDIM + col] = make_float2(oacc[j][2], oacc[j][3]);
    }
}

// ---------------------------------------------------------------------------
extern "C" void kernel_launch(void* const* d_in, const int* in_sizes, int n_in,
                              void* d_out, int out_size)
{
    const float* Q    = (const float*)d_in[0];
    const float* K    = (const float*)d_in[1];
    const float* V    = (const float*)d_in[2];
    const int*   mask = (const int*)  d_in[3];

    float* out  = (float*)d_out;
    float* attn = out + (size_t)BH * SEQ * DKDIM;

    cudaFuncSetAttribute(stats_pass,   cudaFuncAttributeMaxDynamicSharedMemorySize, S_SMEM);
    cudaFuncSetAttribute(recompute_pv, cudaFuncAttributeMaxDynamicSharedMemorySize, B_SMEM);

    preconv<<<2048, 256>>>(Q, K, V);
    pack_mask<<<1024, 256>>>(mask);
    stats_pass<<<dim3(SEQ / 64, BH), 128, S_SMEM>>>();
    recompute_pv<<<dim3(SEQ / 64, BH), 128, B_SMEM>>>(attn, out);
}

// round 13
// speedup vs baseline: 3.5595x; 1.0996x over previous
#include <cuda_runtime.h>
#include <cuda_fp16.h>
#include <cstdint>
#include <math.h>

#define BATCH 4
#define HEADS 16
#define SEQ   2048
#define DKDIM 64
#define BH    (BATCH*HEADS)
#define NELEM (BH*SEQ*DKDIM)   // 8,388,608

// Scratch (allowed: __device__ global arrays)
__device__ float g_M[BH * SEQ];
__device__ float g_L[BH * SEQ];
__device__ __half g_Qh[NELEM];                // Q fp16
__device__ __half g_Kh[NELEM];                // K fp16
__device__ __half g_Vh[NELEM];                // V fp16
__device__ unsigned long long g_Mb[BATCH * SEQ * (SEQ / 64)];  // bit-packed mask, 2 MB

// ---------------------------------------------------------------------------
// PTX helpers
// ---------------------------------------------------------------------------
__device__ __forceinline__ uint32_t smem_u32(const void* p) {
    uint32_t a;
    asm("{ .reg .u64 t; cvta.to.shared.u64 t, %1; cvt.u32.u64 %0, t; }"
        : "=r"(a) : "l"(p));
    return a;
}
__device__ __forceinline__ void ldsm_x4(uint32_t (&r)[4], uint32_t addr) {
    asm volatile("ldmatrix.sync.aligned.m8n8.x4.shared.b16 {%0,%1,%2,%3}, [%4];"
        : "=r"(r[0]), "=r"(r[1]), "=r"(r[2]), "=r"(r[3]) : "r"(addr));
}
__device__ __forceinline__ void ldsm_x4_t(uint32_t (&r)[4], uint32_t addr) {
    asm volatile("ldmatrix.sync.aligned.m8n8.x4.trans.shared.b16 {%0,%1,%2,%3}, [%4];"
        : "=r"(r[0]), "=r"(r[1]), "=r"(r[2]), "=r"(r[3]) : "r"(addr));
}
__device__ __forceinline__ void mma_f16(float (&c)[4], const uint32_t (&a)[4],
                                        uint32_t b0, uint32_t b1) {
    asm volatile("mma.sync.aligned.m16n8k16.row.col.f32.f16.f16.f32 "
        "{%0,%1,%2,%3}, {%4,%5,%6,%7}, {%8,%9}, {%0,%1,%2,%3};"
        : "+f"(c[0]), "+f"(c[1]), "+f"(c[2]), "+f"(c[3])
        : "r"(a[0]), "r"(a[1]), "r"(a[2]), "r"(a[3]), "r"(b0), "r"(b1));
}
#define CP16(dst, src) \
    asm volatile("cp.async.cg.shared.global [%0], [%1], 16;" \
                 :: "r"(dst), "l"(src) : "memory")
#define CP_COMMIT  asm volatile("cp.async.commit_group;" ::: "memory")
#define CP_WAIT0   asm volatile("cp.async.wait_group 0;" ::: "memory")

#define SW128(b) ((b) ^ (((b) >> 3) & 0x70))

__device__ __forceinline__ uint32_t pack_h2(float x, float y) {
    __half2 h = __floats2half2_rn(x, y);
    return *reinterpret_cast<uint32_t*>(&h);
}
__device__ __forceinline__ void splith2(float x, float y, uint32_t& hi, uint32_t& lo) {
    __half2 h = __floats2half2_rn(x, y);
    hi = *reinterpret_cast<uint32_t*>(&h);
    lo = pack_h2(x - __low2float(h), y - __high2float(h));
}

// ---------------------------------------------------------------------------
// Kernel 0a: preconvert. Q, K, V -> fp16.
// ---------------------------------------------------------------------------
__global__ void preconv(const float* __restrict__ Q, const float* __restrict__ K,
                        const float* __restrict__ V)
{
    const int n2 = NELEM / 2;
    uint32_t* qh = (uint32_t*)g_Qh;
    uint32_t* kh = (uint32_t*)g_Kh;
    uint32_t* vh = (uint32_t*)g_Vh;
    for (int i = blockIdx.x * blockDim.x + threadIdx.x; i < n2;
         i += gridDim.x * blockDim.x) {
        float2 q = ((const float2*)Q)[i];
        float2 k = ((const float2*)K)[i];
        float2 v = ((const float2*)V)[i];
        qh[i] = pack_h2(q.x, q.y);
        kh[i] = pack_h2(k.x, k.y);
        vh[i] = pack_h2(v.x, v.y);
    }
}

// ---------------------------------------------------------------------------
// Kernel 0b: pack mask int32 -> bits. One warp per 64-int chunk (ballot).
// ---------------------------------------------------------------------------
__global__ void pack_mask(const int* __restrict__ mask)
{
    const int lane  = threadIdx.x & 31;
    const int warp  = (blockIdx.x * blockDim.x + threadIdx.x) >> 5;
    const int nwarp = (gridDim.x * blockDim.x) >> 5;
    const int nchunk = BATCH * SEQ * (SEQ / 64);
    for (int c = warp; c < nchunk; c += nwarp) {
        const int* p = mask + (size_t)c * 64;
        unsigned lo = __ballot_sync(0xffffffffu, p[lane] != 0);
        unsigned hi = __ballot_sync(0xffffffffu, p[32 + lane] != 0);
        if (lane == 0)
            g_Mb[c] = ((unsigned long long)hi << 32) | lo;
    }
}

// ---------------------------------------------------------------------------
// Kernel A: softmax stats only. 1-term fp16 QK^T (Qh . Kh).
// CTA: 128 threads (4 warps), 64 q x 2048 k in 32 tiles of 64.
// ---------------------------------------------------------------------------
#define S_Q  0
#define S_KB 8192    // stage buf at 8192 + buf*8192
#define S_SMEM 24576

__global__ __launch_bounds__(128, 4)
void stats_pass()
{
    extern __shared__ char smem[];
    const uint32_t sb = smem_u32(smem);
    const int tid = threadIdx.x, wid = tid >> 5, lane = tid & 31;

    const int bh = blockIdx.y, b = bh >> 4;
    const int qBase = blockIdx.x * 64;

    const char* qhg = (const char*)(g_Qh + (size_t)(bh * SEQ + qBase) * DKDIM);
    #pragma unroll
    for (int i = tid; i < 512; i += 128) {
        const int r = i >> 3, c = i & 7;
        CP16(sb + S_Q + SW128((uint32_t)(r * 128 + c * 16)), qhg + r * 128 + c * 16);
    }

    const char* khg = (const char*)(g_Kh + (size_t)bh * SEQ * DKDIM);
    auto issueK = [&](int kt, int buf) {
        #pragma unroll
        for (int i = tid; i < 512; i += 128) {
            const int r = i >> 3, c = i & 7;
            CP16(sb + S_KB + buf * 8192 + SW128((uint32_t)(r * 128 + c * 16)),
                 khg + (size_t)(kt * 64 + r) * 128 + c * 16);
        }
        CP_COMMIT;
    };
    issueK(0, 0);   // commits Q + K(0) as one group

    const int wm   = wid * 16;
    const int arow = lane & 15;
    const int abyt = (lane >> 4) << 4;
    const int row0 = lane >> 2;
    const int r0g  = qBase + wm + row0;

    const unsigned long long* bmp = g_Mb + (size_t)b * SEQ * 32;
    float m0 = -INFINITY, m1 = -INFINITY, l0 = 0.0f, l1 = 0.0f;

    for (int kt = 0; kt < 32; kt++) {
        CP_WAIT0;
        __syncthreads();
        if (kt + 1 < 32) issueK(kt + 1, (kt + 1) & 1);

        const unsigned long long mb0 = bmp[(size_t)r0g * 32 + kt];
        const unsigned long long mb1 = bmp[(size_t)(r0g + 8) * 32 + kt];

        const uint32_t sq = sb + S_Q;
        const uint32_t sk = sb + S_KB + (kt & 1) * 8192;

        float acc[8][4];
        #pragma unroll
        for (int j = 0; j < 8; j++)
            #pragma unroll
            for (int e = 0; e < 4; e++) acc[j][e] = 0.0f;

        #pragma unroll
        for (int ks = 0; ks < 4; ks++) {
            uint32_t a[4];
            ldsm_x4(a, sq + SW128((uint32_t)((wm + arow) * 128 + ks * 32 + abyt)));
            #pragma unroll
            for (int nb = 0; nb < 4; nb++) {
                uint32_t bh4[4];
                ldsm_x4(bh4, sk + SW128((uint32_t)((nb * 16 + arow) * 128 + ks * 32 + abyt)));
                mma_f16(acc[nb*2],   a, bh4[0], bh4[2]);
                mma_f16(acc[nb*2+1], a, bh4[1], bh4[3]);
            }
        }

        float tmx0 = -INFINITY, tmx1 = -INFINITY;
        #pragma unroll
        for (int nj = 0; nj < 8; nj++) {
            const int c0 = nj * 8 + (lane & 3) * 2;
            acc[nj][0] = ((mb0 >> c0) & 1)       ? acc[nj][0] * 0.125f : -1e9f;
            acc[nj][1] = ((mb0 >> (c0 + 1)) & 1) ? acc[nj][1] * 0.125f : -1e9f;
            acc[nj][2] = ((mb1 >> c0) & 1)       ? acc[nj][2] * 0.125f : -1e9f;
            acc[nj][3] = ((mb1 >> (c0 + 1)) & 1) ? acc[nj][3] * 0.125f : -1e9f;
            tmx0 = fmaxf(tmx0, fmaxf(acc[nj][0], acc[nj][1]));
            tmx1 = fmaxf(tmx1, fmaxf(acc[nj][2], acc[nj][3]));
        }
        tmx0 = fmaxf(tmx0, __shfl_xor_sync(0xffffffffu, tmx0, 1));
        tmx0 = fmaxf(tmx0, __shfl_xor_sync(0xffffffffu, tmx0, 2));
        tmx1 = fmaxf(tmx1, __shfl_xor_sync(0xffffffffu, tmx1, 1));
        tmx1 = fmaxf(tmx1, __shfl_xor_sync(0xffffffffu, tmx1, 2));

        const float m0n = fmaxf(m0, tmx0);
        const float m1n = fmaxf(m1, tmx1);
        float s0 = 0.0f, s1 = 0.0f;
        #pragma unroll
        for (int nj = 0; nj < 8; nj++) {
            s0 += __expf(acc[nj][0] - m0n) + __expf(acc[nj][1] - m0n);
            s1 += __expf(acc[nj][2] - m1n) + __expf(acc[nj][3] - m1n);
        }
        s0 += __shfl_xor_sync(0xffffffffu, s0, 1);
        s0 += __shfl_xor_sync(0xffffffffu, s0, 2);
        s1 += __shfl_xor_sync(0xffffffffu, s1, 1);
        s1 += __shfl_xor_sync(0xffffffffu, s1, 2);

        l0 = l0 * __expf(m0 - m0n) + s0;  m0 = m0n;
        l1 = l1 * __expf(m1 - m1n) + s1;  m1 = m1n;
    }

    if ((lane & 3) == 0) {
        g_M[(size_t)bh * SEQ + r0g]     = m0;
        g_L[(size_t)bh * SEQ + r0g]     = l0;
        g_M[(size_t)bh * SEQ + r0g + 8] = m1;
        g_L[(size_t)bh * SEQ + r0g + 8] = l1;
    }
}

// ---------------------------------------------------------------------------
// Kernel B: recompute QK^T (1-term Qh.Kh — bit-identical to stats_pass),
// normalize, write attn once, out += P.V (Ph.Vh + Pl.Vh, P split in regs).
// Per-ks fused epilogue+PV. SMEM ~41.5 KB, (128,4).
// ---------------------------------------------------------------------------
#define B_QH  0
#define B_KB  8192     // K stage buf at 8192 + buf*8192
#define B_VB  24576    // V stage buf at 24576 + buf*8192
#define B_M   40960
#define B_IL  41216
#define B_SMEM 41472

__global__ __launch_bounds__(128, 4)
void recompute_pv(float* __restrict__ attn, float* __restrict__ out)
{
    extern __shared__ char smem[];
    const uint32_t sb = smem_u32(smem);
    const int tid = threadIdx.x, wid = tid >> 5, lane = tid & 31;

    const int bh = blockIdx.y, b = bh >> 4;
    const int qBase = blockIdx.x * 64;

    float* sm_m  = (float*)(smem + B_M);
    float* sm_il = (float*)(smem + B_IL);
    if (tid < 64) {
        sm_m[tid]  = g_M[(size_t)bh * SEQ + qBase + tid];
        sm_il[tid] = 1.0f / g_L[(size_t)bh * SEQ + qBase + tid];
    }

    const char* qhg = (const char*)(g_Qh + (size_t)(bh * SEQ + qBase) * DKDIM);
    #pragma unroll
    for (int i = tid; i < 512; i += 128) {
        const int r = i >> 3, c = i & 7;
        CP16(sb + B_QH + SW128((uint32_t)(r * 128 + c * 16)), qhg + r * 128 + c * 16);
    }

    const char* khg = (const char*)(g_Kh + (size_t)bh * SEQ * DKDIM);
    const char* vhg = (const char*)(g_Vh + (size_t)bh * SEQ * DKDIM);

    auto issueKV = [&](int kt, int buf) {
        #pragma unroll
        for (int i = tid; i < 512; i += 128) {
            const int r = i >> 3, c = i & 7;
            const uint32_t sw = SW128((uint32_t)(r * 128 + c * 16));
            CP16(sb + B_KB + buf * 8192 + sw, khg + (size_t)(kt * 64 + r) * 128 + c * 16);
            CP16(sb + B_VB + buf * 8192 + sw, vhg + (size_t)(kt * 64 + r) * 128 + c * 16);
        }
        CP_COMMIT;
    };
    issueKV(0, 0);
    __syncthreads();

    const int wm   = wid * 16;
    const int arow = lane & 15;
    const int abyt = (lane >> 4) << 4;
    const int row0 = lane >> 2;
    const int r0g  = qBase + wm + row0;

    const float m0r  = sm_m[wm + row0],  m8r  = sm_m[wm + row0 + 8];
    const float il0r = sm_il[wm + row0], il8r = sm_il[wm + row0 + 8];

    const unsigned long long* bmp = g_Mb + (size_t)b * SEQ * 32;
    float* ap = attn + (size_t)bh * SEQ * SEQ;

    float oacc[8][4];
    #pragma unroll
    for (int j = 0; j < 8; j++)
        #pragma unroll
        for (int e = 0; e < 4; e++) oacc[j][e] = 0.0f;

    for (int kt = 0; kt < 32; kt++) {
        CP_WAIT0;
        __syncthreads();
        if (kt + 1 < 32) issueKV(kt + 1, (kt + 1) & 1);

        const unsigned long long mb0 = bmp[(size_t)r0g * 32 + kt];
        const unsigned long long mb1 = bmp[(size_t)(r0g + 8) * 32 + kt];

        const int buf = kt & 1;
        const uint32_t sq  = sb + B_QH;
        const uint32_t skh = sb + B_KB + buf * 8192;
        const uint32_t sv  = sb + B_VB + buf * 8192;

        // ---- QK^T: 1-term fp16 (identical s to stats_pass) ----
        float acc[8][4];
        #pragma unroll
        for (int j = 0; j < 8; j++)
            #pragma unroll
            for (int e = 0; e < 4; e++) acc[j][e] = 0.0f;

        #pragma unroll
        for (int ks = 0; ks < 4; ks++) {
            uint32_t a[4];
            ldsm_x4(a, sq + SW128((uint32_t)((wm + arow) * 128 + ks * 32 + abyt)));
            #pragma unroll
            for (int nb = 0; nb < 4; nb++) {
                uint32_t bh4[4];
                ldsm_x4(bh4, skh + SW128((uint32_t)((nb * 16 + arow) * 128 + ks * 32 + abyt)));
                mma_f16(acc[nb*2],   a, bh4[0], bh4[2]);
                mma_f16(acc[nb*2+1], a, bh4[1], bh4[3]);
            }
        }

        // ---- per-ks: normalize + write attn + build fragments + PV MMAs ----
        #pragma unroll
        for (int ks = 0; ks < 4; ks++) {
            uint32_t ph[4], pl[4];
            #pragma unroll
            for (int half = 0; half < 2; half++) {
                const int nj  = ks * 2 + half;
                const int c0  = nj * 8 + (lane & 3) * 2;
                const int col = kt * 64 + c0;
                const size_t o0 = (size_t)r0g * SEQ + col;
                const size_t o1 = o0 + (size_t)8 * SEQ;
                float2 p0, p1;
                p0.x = __expf((((mb0 >> c0) & 1)       ? acc[nj][0] * 0.125f : -1e9f) - m0r) * il0r;
                p0.y = __expf((((mb0 >> (c0 + 1)) & 1) ? acc[nj][1] * 0.125f : -1e9f) - m0r) * il0r;
                p1.x = __expf((((mb1 >> c0) & 1)       ? acc[nj][2] * 0.125f : -1e9f) - m8r) * il8r;
                p1.y = __expf((((mb1 >> (c0 + 1)) & 1) ? acc[nj][3] * 0.125f : -1e9f) - m8r) * il8r;
                *(float2*)&ap[o0] = p0;
                *(float2*)&ap[o1] = p1;
                splith2(p0.x, p0.y, ph[half*2],   pl[half*2]);
                splith2(p1.x, p1.y, ph[half*2+1], pl[half*2+1]);
            }
            #pragma unroll
            for (int ng = 0; ng < 4; ng++) {
                uint32_t bh4[4];
                ldsm_x4_t(bh4, sv + SW128((uint32_t)((ks * 16 + arow) * 128 + ng * 32 + abyt)));
                mma_f16(oacc[ng*2],   ph, bh4[0], bh4[1]);
                mma_f16(oacc[ng*2+1], ph, bh4[2], bh4[3]);
                mma_f16(oacc[ng*2],   pl, bh4[0], bh4[1]);
                mma_f16(oacc[ng*2+1], pl, bh4[2], bh4[3]);
            }
        }
    }

    float* op = out + (size_t)bh * SEQ * DKDIM;
    #pragma unroll
    for (int j = 0; j < 8; j++) {
        const int col = j * 8 + (lane & 3) * 2;
        *(float2*)&op[(size_t)r0g * DKDIM + col]       = make_float2(oacc[j][0], oacc[j][1]);
        *(float2*)&op[(size_t)(r0g + 8) * DKDIM + col] = make_float2(oacc[j][2], oacc[j][3]);
    }
}

// ---------------------------------------------------------------------------
extern "C" void kernel_launch(void* const* d_in, const int* in_sizes, int n_in,
                              void* d_out, int out_size)
{
    const float* Q    = (const float*)d_in[0];
    const float* K    = (const float*)d_in[1];
    const float* V    = (const float*)d_in[2];
    const int*   mask = (const int*)  d_in[3];

    float* out  = (float*)d_out;
    float* attn = out + (size_t)BH * SEQ * DKDIM;

    cudaFuncSetAttribute(stats_pass,   cudaFuncAttributeMaxDynamicSharedMemorySize, S_SMEM);
    cudaFuncSetAttribute(recompute_pv, cudaFuncAttributeMaxDynamicSharedMemorySize, B_SMEM);

    preconv<<<2048, 256>>>(Q, K, V);
    pack_mask<<<1024, 256>>>(mask);
    stats_pass<<<dim3(SEQ / 64, BH), 128, S_SMEM>>>();
    recompute_pv<<<dim3(SEQ / 64, BH), 128, B_SMEM>>>(attn, out);
}